// round 5
// baseline (speedup 1.0000x reference)
#include <cuda_runtime.h>
#include <math.h>

#define BB 8
#define CC 256
#define HH 128
#define WW 128
#define NN (HH*WW)          // 16384
#define NPOS 256
#define NHARD 96
#define NRAND 32
#define TEMP_INV (1.0f/0.07f)

#define DSTR 260            // padded pixel-major row stride (floats)
#define NB_MAIN (BB*NN/64)  // 2048 main blocks (64 px each)
#define NB_HARD (BB*NPOS)   // 2048 hard blocks

typedef unsigned long long u64;

__device__ __forceinline__ u64 fma2(u64 a, u64 b, u64 c) {
    u64 d;
    asm("fma.rn.f32x2 %0,%1,%2,%3;" : "=l"(d) : "l"(a), "l"(b), "l"(c));
    return d;
}
__device__ __forceinline__ float2 unpack2(u64 v) {
    float2 f;
    asm("mov.b64 {%0,%1},%2;" : "=f"(f.x), "=f"(f.y) : "l"(v));
    return f;
}

// ---------------- scratch (static device globals; no allocation) ------------
__device__ float g_rgbT[BB*NN*CC];      // normalized rgb, [b][pixel][channel]
__device__ float g_pos[BB*NN];
__device__ float g_lse[BB*NN];
__device__ float g_maxneg[BB*NN];
__device__ float g_lse_hard[BB*NPOS];
__device__ float g_max_hard[BB*NPOS];
__device__ float g_acc[3];              // loss_sum, mask_sum, correct_sum

// ---------------- kernel 1: normalize + transpose rgb -> g_rgbT --------------
__global__ __launch_bounds__(256) void k_norm_t(const float* __restrict__ in) {
    __shared__ float s_tile[CC*33];
    __shared__ float s_red[8*33];
    __shared__ float s_inv[32];
    const int tid = threadIdx.x;
    const int tx = tid & 31;        // pixel in tile
    const int ty = tid >> 5;        // channel group
    const int blocksPerBatch = NN/32;
    const int b  = blockIdx.x / blocksPerBatch;
    const int n0 = (blockIdx.x % blocksPerBatch) * 32;

    if (blockIdx.x == 0 && tid < 3) g_acc[tid] = 0.0f;

    const float* src = in + b*CC*NN + n0;
    #pragma unroll 8
    for (int i = 0; i < 32; i++) {
        int c = i*8 + ty;
        s_tile[c*33 + tx] = src[c*NN + tx];
    }
    __syncthreads();

    float ss = 0.0f;
    #pragma unroll
    for (int j = 0; j < 32; j++) {
        float v = s_tile[(ty*32 + j)*33 + tx];
        ss += v*v;
    }
    s_red[ty*33 + tx] = ss;
    __syncthreads();
    if (ty == 0) {
        float t = 0.0f;
        #pragma unroll
        for (int j = 0; j < 8; j++) t += s_red[j*33 + tx];
        s_inv[tx] = 1.0f / fmaxf(sqrtf(t), 1e-12f);
    }
    __syncthreads();

    float* dst = g_rgbT + (b*NN + n0)*CC;
    const int cb = tid & 63;
    const int pq = tid >> 6;
    #pragma unroll
    for (int it = 0; it < 8; it++) {
        int px = it*4 + pq;
        float inv = s_inv[px];
        float4 v;
        v.x = s_tile[(cb*4+0)*33 + px] * inv;
        v.y = s_tile[(cb*4+1)*33 + px] * inv;
        v.z = s_tile[(cb*4+2)*33 + px] * inv;
        v.w = s_tile[(cb*4+3)*33 + px] * inv;
        reinterpret_cast<float4*>(dst + px*CC)[cb] = v;
    }
}

// ---------------- kernel 2: fused main (64px, R3 layout) + hard blocks -------
__device__ __forceinline__ int corner_idx(int xx, int yy, float& w) {
    bool v = (xx >= 0) & (xx < WW) & (yy >= 0) & (yy < HH);
    if (!v) w = 0.0f;
    int cx = min(max(xx, 0), WW-1);
    int cy = min(max(yy, 0), HH-1);
    return cy*WW + cx;
}

__global__ __launch_bounds__(256) void k_fused(const float* __restrict__ dep,
                                               const float* __restrict__ proj,
                                               const int*   __restrict__ rand_idx,
                                               const int*   __restrict__ offu,
                                               const int*   __restrict__ offv) {
    extern __shared__ float sm[];
    const int tid = threadIdx.x;
    const int tx  = tid & 31;
    const int ty  = tid >> 5;

    if (blockIdx.x >= NB_MAIN) {
        // ================= HARD-NEGATIVE BLOCK (self-normalizing) ============
        float* s_depv = sm;              // 256
        float* s_hsim = sm + CC;         // 96
        float* s_red2 = s_hsim + NHARD;  // 8
        float* s_invd = s_red2 + 8;      // 1
        const int hb = blockIdx.x - NB_MAIN;
        const int b = hb >> 8;
        const int p = hb & 255;
        const int gh = (p >> 4) * 8;
        const int gw = (p & 15) * 8;
        const int ng = gh*WW + gw;

        float v = dep[b*CC*NN + tid*NN + ng];
        {
            float ss = v*v;
            #pragma unroll
            for (int o = 16; o; o >>= 1) ss += __shfl_xor_sync(0xffffffffu, ss, o);
            if (tx == 0) s_red2[ty] = ss;
        }
        __syncthreads();
        if (tid == 0) {
            float t = 0.0f;
            #pragma unroll
            for (int j = 0; j < 8; j++) t += s_red2[j];
            s_invd[0] = TEMP_INV / fmaxf(sqrtf(t), 1e-12f);
        }
        __syncthreads();
        s_depv[tid] = v * s_invd[0];
        __syncthreads();

        float pu = proj[b*2*NN + ng];
        float pv = proj[b*2*NN + NN + ng];
        int posu = (int)fminf(fmaxf(pu, 0.0f), (float)(WW-1));
        int posv = (int)fminf(fmaxf(pv, 0.0f), (float)(HH-1));

        const float4* dv = reinterpret_cast<const float4*>(s_depv);
        #pragma unroll
        for (int g3 = 0; g3 < 3; g3++) {
            int hbase = ty*12 + g3*4;
            const float4* r[4];
            #pragma unroll
            for (int j = 0; j < 4; j++) {
                int h = hbase + j;
                int ou = offu[(b*NHARD + h)*NPOS + p];
                int ov = offv[(b*NHARD + h)*NPOS + p];
                if (ou == 0 && ov == 0) ou = 1;
                int hu = min(max(posu + ou, 0), WW-1);
                int hv = min(max(posv + ov, 0), HH-1);
                r[j] = reinterpret_cast<const float4*>(g_rgbT + (b*NN + hv*WW + hu)*CC);
            }
            float a0 = 0.f, a1 = 0.f, a2 = 0.f, a3 = 0.f;
            #pragma unroll
            for (int jj = 0; jj < 2; jj++) {
                int c4 = jj*32 + tx;
                float4 d = dv[c4];
                float4 v0 = r[0][c4];
                float4 v1 = r[1][c4];
                float4 v2 = r[2][c4];
                float4 v3 = r[3][c4];
                a0 += d.x*v0.x; a0 += d.y*v0.y; a0 += d.z*v0.z; a0 += d.w*v0.w;
                a1 += d.x*v1.x; a1 += d.y*v1.y; a1 += d.z*v1.z; a1 += d.w*v1.w;
                a2 += d.x*v2.x; a2 += d.y*v2.y; a2 += d.z*v2.z; a2 += d.w*v2.w;
                a3 += d.x*v3.x; a3 += d.y*v3.y; a3 += d.z*v3.z; a3 += d.w*v3.w;
            }
            #pragma unroll
            for (int o = 16; o; o >>= 1) {
                a0 += __shfl_xor_sync(0xffffffffu, a0, o);
                a1 += __shfl_xor_sync(0xffffffffu, a1, o);
                a2 += __shfl_xor_sync(0xffffffffu, a2, o);
                a3 += __shfl_xor_sync(0xffffffffu, a3, o);
            }
            if (tx == 0) {
                s_hsim[hbase+0] = a0;
                s_hsim[hbase+1] = a1;
                s_hsim[hbase+2] = a2;
                s_hsim[hbase+3] = a3;
            }
        }
        __syncthreads();

        if (tid < 32) {
            float v0 = s_hsim[tx];
            float v1 = s_hsim[tx + 32];
            float v2 = s_hsim[tx + 64];
            float m = fmaxf(fmaxf(v0, v1), v2);
            #pragma unroll
            for (int o = 16; o; o >>= 1) m = fmaxf(m, __shfl_xor_sync(0xffffffffu, m, o));
            float se = expf(v0 - m) + expf(v1 - m) + expf(v2 - m);
            #pragma unroll
            for (int o = 16; o; o >>= 1) se += __shfl_xor_sync(0xffffffffu, se, o);
            if (tx == 0) {
                g_lse_hard[b*NPOS + p] = m + logf(se);
                g_max_hard[b*NPOS + p] = m;
            }
        }
        return;
    }

    // ================= MAIN BLOCK (64 pixels, R3 layout) =====================
    float* s_dep2 = sm;                        // 64 * 260, pixel-major
    float* s_rand = s_dep2 + 64*DSTR;          // 32 * 256
    float* s_sim  = s_rand + NRAND*CC;         // 32 * 65
    float* s_pos  = s_sim + NRAND*65;          // 64
    float* s_inv  = s_pos + 64;                // 64
    float* s_red  = s_inv + 64;                // 4 * 65

    const int blocksPerBatch = NN/64;
    const int b  = blockIdx.x / blocksPerBatch;
    const int n0 = (blockIdx.x % blocksPerBatch) * 64;

    // ---- stage dep tile pixel-major + partial norms ----
    {
        const int px = tid & 63;               // pixel 0..63
        const int cg = tid >> 6;               // channel group 0..3
        const float* dsrc = dep + b*CC*NN + n0 + px;
        float ss = 0.0f;
        #pragma unroll 16
        for (int i = 0; i < 64; i++) {
            int c = i*4 + cg;
            float v = dsrc[c*NN];
            s_dep2[px*DSTR + c] = v;
            ss += v*v;
        }
        s_red[cg*65 + px] = ss;
    }
    // ---- stage rand vectors ----
    {
        int k = tid >> 3, part = tid & 7;
        int ridx = rand_idx[b*NRAND + k];
        const float4* row = reinterpret_cast<const float4*>(g_rgbT + (b*NN + ridx)*CC);
        float4* dstr = reinterpret_cast<float4*>(s_rand + k*CC);
        #pragma unroll
        for (int i = 0; i < 8; i++) dstr[part + 8*i] = row[part + 8*i];
    }
    __syncthreads();
    if (tid < 64) {
        float t = s_red[tid] + s_red[65 + tid] + s_red[2*65 + tid] + s_red[3*65 + tid];
        s_inv[tid] = 1.0f / fmaxf(sqrtf(t), 1e-12f);
    }
    __syncthreads();

    // ---- phase 2: pos_sim (warp handles 8 pixels) ----
    const float* projU = proj + b*2*NN;
    const float* projV = projU + NN;
    const float4* dv4 = reinterpret_cast<const float4*>(s_dep2);
    #pragma unroll
    for (int q = 0; q < 8; q++) {
        int px = ty*8 + q;
        int n  = n0 + px;
        float pu = projU[n], pv = projV[n];
        float x0f = floorf(pu), y0f = floorf(pv);
        float wx = pu - x0f, wy = pv - y0f;
        int x0 = (int)x0f, y0 = (int)y0f;
        float w00 = (1.0f-wx)*(1.0f-wy), w10 = wx*(1.0f-wy);
        float w01 = (1.0f-wx)*wy,        w11 = wx*wy;
        int i00 = corner_idx(x0,   y0,   w00);
        int i10 = corner_idx(x0+1, y0,   w10);
        int i01 = corner_idx(x0,   y0+1, w01);
        int i11 = corner_idx(x0+1, y0+1, w11);
        const float4* r00 = reinterpret_cast<const float4*>(g_rgbT + (b*NN + i00)*CC);
        const float4* r10 = reinterpret_cast<const float4*>(g_rgbT + (b*NN + i10)*CC);
        const float4* r01 = reinterpret_cast<const float4*>(g_rgbT + (b*NN + i01)*CC);
        const float4* r11 = reinterpret_cast<const float4*>(g_rgbT + (b*NN + i11)*CC);
        float pacc = 0.0f;
        #pragma unroll
        for (int jj = 0; jj < 2; jj++) {
            int c4 = tx + jj*32;
            float4 d  = dv4[px*(DSTR/4) + c4];
            float4 a00 = r00[c4], a10 = r10[c4], a01 = r01[c4], a11 = r11[c4];
            pacc += d.x*(w00*a00.x + w10*a10.x + w01*a01.x + w11*a11.x);
            pacc += d.y*(w00*a00.y + w10*a10.y + w01*a01.y + w11*a11.y);
            pacc += d.z*(w00*a00.z + w10*a10.z + w01*a01.z + w11*a11.z);
            pacc += d.w*(w00*a00.w + w10*a10.w + w01*a01.w + w11*a11.w);
        }
        #pragma unroll
        for (int o = 16; o; o >>= 1) pacc += __shfl_xor_sync(0xffffffffu, pacc, o);
        if (tx == 0) s_pos[px] = pacc;
    }

    // ---- phase 3: rand dots, 2 pixels/lane, 4 k's/warp, f32x2 FMA ----
    {
        const ulonglong2* dA = reinterpret_cast<const ulonglong2*>(s_dep2 + tx*DSTR);
        const ulonglong2* dB = reinterpret_cast<const ulonglong2*>(s_dep2 + (tx+32)*DSTR);
        const ulonglong2* rp0 = reinterpret_cast<const ulonglong2*>(s_rand + (ty*4+0)*CC);
        const ulonglong2* rp1 = reinterpret_cast<const ulonglong2*>(s_rand + (ty*4+1)*CC);
        const ulonglong2* rp2 = reinterpret_cast<const ulonglong2*>(s_rand + (ty*4+2)*CC);
        const ulonglong2* rp3 = reinterpret_cast<const ulonglong2*>(s_rand + (ty*4+3)*CC);
        u64 aA0=0, aA1=0, aA2=0, aA3=0;
        u64 aB0=0, aB1=0, aB2=0, aB3=0;
        #pragma unroll 8
        for (int c4 = 0; c4 < 64; c4++) {
            ulonglong2 da = dA[c4];
            ulonglong2 db = dB[c4];
            ulonglong2 r0 = rp0[c4], r1 = rp1[c4], r2 = rp2[c4], r3 = rp3[c4];
            aA0 = fma2(da.x, r0.x, aA0); aA0 = fma2(da.y, r0.y, aA0);
            aA1 = fma2(da.x, r1.x, aA1); aA1 = fma2(da.y, r1.y, aA1);
            aA2 = fma2(da.x, r2.x, aA2); aA2 = fma2(da.y, r2.y, aA2);
            aA3 = fma2(da.x, r3.x, aA3); aA3 = fma2(da.y, r3.y, aA3);
            aB0 = fma2(db.x, r0.x, aB0); aB0 = fma2(db.y, r0.y, aB0);
            aB1 = fma2(db.x, r1.x, aB1); aB1 = fma2(db.y, r1.y, aB1);
            aB2 = fma2(db.x, r2.x, aB2); aB2 = fma2(db.y, r2.y, aB2);
            aB3 = fma2(db.x, r3.x, aB3); aB3 = fma2(db.y, r3.y, aB3);
        }
        float2 f;
        f = unpack2(aA0); s_sim[(ty*4+0)*65 + tx]      = f.x + f.y;
        f = unpack2(aA1); s_sim[(ty*4+1)*65 + tx]      = f.x + f.y;
        f = unpack2(aA2); s_sim[(ty*4+2)*65 + tx]      = f.x + f.y;
        f = unpack2(aA3); s_sim[(ty*4+3)*65 + tx]      = f.x + f.y;
        f = unpack2(aB0); s_sim[(ty*4+0)*65 + tx + 32] = f.x + f.y;
        f = unpack2(aB1); s_sim[(ty*4+1)*65 + tx + 32] = f.x + f.y;
        f = unpack2(aB2); s_sim[(ty*4+2)*65 + tx + 32] = f.x + f.y;
        f = unpack2(aB3); s_sim[(ty*4+3)*65 + tx + 32] = f.x + f.y;
    }
    __syncthreads();

    // ---- phase 4: per-pixel logsumexp / max, lane-parallel over negatives ----
    #pragma unroll
    for (int q = 0; q < 8; q++) {
        int px = ty*8 + q;
        float scale = s_inv[px] * TEMP_INV;
        float pos = s_pos[px] * scale;
        float v = s_sim[tx*65 + px] * scale;
        float mneg = v;
        #pragma unroll
        for (int o = 16; o; o >>= 1) mneg = fmaxf(mneg, __shfl_xor_sync(0xffffffffu, mneg, o));
        float m = fmaxf(pos, mneg);
        float e = expf(v - m);
        #pragma unroll
        for (int o = 16; o; o >>= 1) e += __shfl_xor_sync(0xffffffffu, e, o);
        if (tx == 0) {
            int gp = b*NN + n0 + px;
            g_pos[gp]    = pos;
            g_lse[gp]    = m + logf(e + expf(pos - m));
            g_maxneg[gp] = mneg;
        }
    }
}

// ---------------- kernel 4: loss/accuracy reduction ---------------------------
__global__ __launch_bounds__(256) void k_loss(const float* __restrict__ valid) {
    __shared__ float sA[8], sB[8], sC[8];
    const int g = blockIdx.x * 256 + threadIdx.x;
    const int b = g >> 14;
    const int n = g & (NN-1);
    const int vq = n >> 7;
    const int u  = n & 127;

    float lse = g_lse[g];
    float pos = g_pos[g];
    float mx  = g_maxneg[g];
    if (((vq & 7) == 0) && ((u & 7) == 0)) {
        int p = (vq >> 3) * 16 + (u >> 3);
        float lh = g_lse_hard[b*NPOS + p];
        float mh = g_max_hard[b*NPOS + p];
        float m = fmaxf(lse, lh);
        lse = m + logf(expf(lse - m) + expf(lh - m));
        mx = fmaxf(mx, mh);
    }
    float mask = valid[g];
    float lossp = (lse - pos) * mask;
    float corr = (pos > mx && mask > 0.5f) ? 1.0f : 0.0f;
    float mk = mask;

    #pragma unroll
    for (int o = 16; o; o >>= 1) {
        lossp += __shfl_xor_sync(0xffffffffu, lossp, o);
        mk    += __shfl_xor_sync(0xffffffffu, mk,    o);
        corr  += __shfl_xor_sync(0xffffffffu, corr,  o);
    }
    if ((threadIdx.x & 31) == 0) {
        sA[threadIdx.x >> 5] = lossp;
        sB[threadIdx.x >> 5] = mk;
        sC[threadIdx.x >> 5] = corr;
    }
    __syncthreads();
    if (threadIdx.x == 0) {
        float a = 0.f, bb2 = 0.f, c2 = 0.f;
        #pragma unroll
        for (int j = 0; j < 8; j++) { a += sA[j]; bb2 += sB[j]; c2 += sC[j]; }
        atomicAdd(&g_acc[0], a);
        atomicAdd(&g_acc[1], bb2);
        atomicAdd(&g_acc[2], c2);
    }
}

// ---------------- kernel 5: epilogue ------------------------------------------
__global__ void k_out(float* out) {
    float denom = fmaxf(g_acc[1], 1.0f);
    out[0] = g_acc[0] / denom;
    out[1] = g_acc[2] / denom * 100.0f;
}

// ---------------- launch -------------------------------------------------------
extern "C" void kernel_launch(void* const* d_in, const int* in_sizes, int n_in,
                              void* d_out, int out_size) {
    const float* rgb   = (const float*)d_in[0];
    const float* dep   = (const float*)d_in[1];
    const float* proj  = (const float*)d_in[2];
    const float* valid = (const float*)d_in[3];
    const int*   ridx  = (const int*)d_in[4];
    const int*   offu  = (const int*)d_in[5];
    const int*   offv  = (const int*)d_in[6];
    float* out = (float*)d_out;

    const int smem_fused = (64*DSTR + NRAND*CC + NRAND*65 + 64 + 64 + 4*65) * (int)sizeof(float);
    cudaFuncSetAttribute(k_fused, cudaFuncAttributeMaxDynamicSharedMemorySize, smem_fused);

    k_norm_t<<<BB*NN/32, 256>>>(rgb);
    k_fused<<<NB_MAIN + NB_HARD, 256, smem_fused>>>(dep, proj, ridx, offu, offv);
    k_loss<<<BB*NN/256, 256>>>(valid);
    k_out<<<1, 1>>>(out);
}

// round 6
// speedup vs baseline: 1.6583x; 1.6583x over previous
#include <cuda_runtime.h>
#include <cuda_fp16.h>
#include <math.h>

#define BB 8
#define CC 256
#define HH 128
#define WW 128
#define NN (HH*WW)          // 16384
#define NPOS 256
#define NHARD 96
#define NRAND 32
#define TEMP_INV (1.0f/0.07f)

#define DSTR 260            // padded pixel-major row stride (floats)

typedef unsigned long long u64;

__device__ __forceinline__ u64 fma2(u64 a, u64 b, u64 c) {
    u64 d;
    asm("fma.rn.f32x2 %0,%1,%2,%3;" : "=l"(d) : "l"(a), "l"(b), "l"(c));
    return d;
}
__device__ __forceinline__ float2 unpack2(u64 v) {
    float2 f;
    asm("mov.b64 {%0,%1},%2;" : "=f"(f.x), "=f"(f.y) : "l"(v));
    return f;
}

// ---------------- scratch (static device globals; no allocation) ------------
__device__ __half g_rgbTh[BB*NN*CC];    // normalized rgb (fp16), [b][px][ch]
__device__ float g_depGrid[BB*NPOS*CC]; // normalized*TEMP_INV dep at grid pts
__device__ float g_pos[BB*NN];
__device__ float g_lse[BB*NN];
__device__ float g_maxneg[BB*NN];
__device__ float g_lse_hard[BB*NPOS];
__device__ float g_max_hard[BB*NPOS];
__device__ float g_acc[3];              // loss_sum, mask_sum, correct_sum

// ---------------- kernel 1: normalize + transpose rgb -> g_rgbTh -------------
__global__ __launch_bounds__(256) void k_norm_t(const float* __restrict__ in) {
    __shared__ float s_tile[CC*33];
    __shared__ float s_red[8*33];
    __shared__ float s_inv[32];
    const int tid = threadIdx.x;
    const int tx = tid & 31;        // pixel in tile
    const int ty = tid >> 5;        // channel group
    const int blocksPerBatch = NN/32;
    const int b  = blockIdx.x / blocksPerBatch;
    const int n0 = (blockIdx.x % blocksPerBatch) * 32;

    if (blockIdx.x == 0 && tid < 3) g_acc[tid] = 0.0f;

    const float* src = in + b*CC*NN + n0;
    #pragma unroll 8
    for (int i = 0; i < 32; i++) {
        int c = i*8 + ty;
        s_tile[c*33 + tx] = src[c*NN + tx];
    }
    __syncthreads();

    float ss = 0.0f;
    #pragma unroll
    for (int j = 0; j < 32; j++) {
        float v = s_tile[(ty*32 + j)*33 + tx];
        ss += v*v;
    }
    s_red[ty*33 + tx] = ss;
    __syncthreads();
    if (ty == 0) {
        float t = 0.0f;
        #pragma unroll
        for (int j = 0; j < 8; j++) t += s_red[j*33 + tx];
        s_inv[tx] = 1.0f / fmaxf(sqrtf(t), 1e-12f);
    }
    __syncthreads();

    // write transposed+normalized rows as fp16: 32 uint4 chunks (8 ch) per row
    __half* dst = g_rgbTh + (size_t)(b*NN + n0)*CC;
    const int cb = tid & 31;        // chunk 0..31 (channels cb*8..cb*8+7)
    const int pq = tid >> 5;        // pixel sub-index 0..7
    #pragma unroll
    for (int it = 0; it < 4; it++) {
        int px = it*8 + pq;
        float inv = s_inv[px];
        float v[8];
        #pragma unroll
        for (int j = 0; j < 8; j++) v[j] = s_tile[(cb*8+j)*33 + px] * inv;
        uint4 q;
        __half2 h;
        h = __floats2half2_rn(v[0], v[1]); q.x = *reinterpret_cast<unsigned*>(&h);
        h = __floats2half2_rn(v[2], v[3]); q.y = *reinterpret_cast<unsigned*>(&h);
        h = __floats2half2_rn(v[4], v[5]); q.z = *reinterpret_cast<unsigned*>(&h);
        h = __floats2half2_rn(v[6], v[7]); q.w = *reinterpret_cast<unsigned*>(&h);
        reinterpret_cast<uint4*>(dst + (size_t)px*CC)[cb] = q;
    }
}

// ---------------- kernel 2: main pass, 64 pixels per block -------------------
__device__ __forceinline__ int corner_idx(int xx, int yy, float& w) {
    bool v = (xx >= 0) & (xx < WW) & (yy >= 0) & (yy < HH);
    if (!v) w = 0.0f;
    int cx = min(max(xx, 0), WW-1);
    int cy = min(max(yy, 0), HH-1);
    return cy*WW + cx;
}

__global__ __launch_bounds__(256) void k_main(const float* __restrict__ dep,
                                              const float* __restrict__ proj,
                                              const int*   __restrict__ rand_idx) {
    extern __shared__ float sm[];
    float* s_dep2 = sm;                        // 64 * 260, pixel-major
    float* s_rand = s_dep2 + 64*DSTR;          // 32 * 256
    float* s_sim  = s_rand + NRAND*CC;         // 32 * 65
    float* s_pos  = s_sim + NRAND*65;          // 64
    float* s_inv  = s_pos + 64;                // 64
    float* s_red  = s_inv + 64;                // 4 * 65

    const int tid = threadIdx.x;
    const int tx  = tid & 31;
    const int ty  = tid >> 5;                  // warp id 0..7
    const int blocksPerBatch = NN/64;
    const int b  = blockIdx.x / blocksPerBatch;
    const int n0 = (blockIdx.x % blocksPerBatch) * 64;

    // ---- stage dep tile pixel-major + partial norms ----
    {
        const int px = tid & 63;               // pixel 0..63
        const int cg = tid >> 6;               // channel group 0..3
        const float* dsrc = dep + b*CC*NN + n0 + px;
        float ss = 0.0f;
        #pragma unroll 16
        for (int i = 0; i < 64; i++) {
            int c = i*4 + cg;
            float v = dsrc[c*NN];
            s_dep2[px*DSTR + c] = v;
            ss += v*v;
        }
        s_red[cg*65 + px] = ss;
    }
    // ---- stage rand vectors (fp16 rows -> fp32 smem) ----
    {
        int k = tid >> 3, part = tid & 7;
        int ridx = rand_idx[b*NRAND + k];
        const uint4* row = reinterpret_cast<const uint4*>(g_rgbTh + (size_t)(b*NN + ridx)*CC);
        float* dstr = s_rand + k*CC;
        #pragma unroll
        for (int i = 0; i < 4; i++) {
            int chunk = part + 8*i;            // channels chunk*8..chunk*8+7
            uint4 q = row[chunk];
            float2 f0 = __half22float2(*reinterpret_cast<__half2*>(&q.x));
            float2 f1 = __half22float2(*reinterpret_cast<__half2*>(&q.y));
            float2 f2 = __half22float2(*reinterpret_cast<__half2*>(&q.z));
            float2 f3 = __half22float2(*reinterpret_cast<__half2*>(&q.w));
            float4* o = reinterpret_cast<float4*>(dstr + chunk*8);
            o[0] = make_float4(f0.x, f0.y, f1.x, f1.y);
            o[1] = make_float4(f2.x, f2.y, f3.x, f3.y);
        }
    }
    __syncthreads();
    if (tid < 64) {
        float t = s_red[tid] + s_red[65 + tid] + s_red[2*65 + tid] + s_red[3*65 + tid];
        s_inv[tid] = 1.0f / fmaxf(sqrtf(t), 1e-12f);
    }
    __syncthreads();

    // ---- phase 2: pos_sim (warp handles 8 pixels), fp16 corner rows ----
    const float* projU = proj + b*2*NN;
    const float* projV = projU + NN;
    const float4* dv4 = reinterpret_cast<const float4*>(s_dep2);
    #pragma unroll
    for (int q = 0; q < 8; q++) {
        int px = ty*8 + q;
        int n  = n0 + px;
        float pu = projU[n], pv = projV[n];
        float x0f = floorf(pu), y0f = floorf(pv);
        float wx = pu - x0f, wy = pv - y0f;
        int x0 = (int)x0f, y0 = (int)y0f;
        float w00 = (1.0f-wx)*(1.0f-wy), w10 = wx*(1.0f-wy);
        float w01 = (1.0f-wx)*wy,        w11 = wx*wy;
        int i00 = corner_idx(x0,   y0,   w00);
        int i10 = corner_idx(x0+1, y0,   w10);
        int i01 = corner_idx(x0,   y0+1, w01);
        int i11 = corner_idx(x0+1, y0+1, w11);
        const uint2* r00 = reinterpret_cast<const uint2*>(g_rgbTh + (size_t)(b*NN + i00)*CC);
        const uint2* r10 = reinterpret_cast<const uint2*>(g_rgbTh + (size_t)(b*NN + i10)*CC);
        const uint2* r01 = reinterpret_cast<const uint2*>(g_rgbTh + (size_t)(b*NN + i01)*CC);
        const uint2* r11 = reinterpret_cast<const uint2*>(g_rgbTh + (size_t)(b*NN + i11)*CC);
        float pacc = 0.0f;
        #pragma unroll
        for (int jj = 0; jj < 2; jj++) {
            int c4 = tx + jj*32;               // 4 channels: c4*4..c4*4+3
            float4 d  = dv4[px*(DSTR/4) + c4];
            uint2 q00 = r00[c4], q10 = r10[c4], q01 = r01[c4], q11 = r11[c4];
            float2 a00lo = __half22float2(*reinterpret_cast<__half2*>(&q00.x));
            float2 a00hi = __half22float2(*reinterpret_cast<__half2*>(&q00.y));
            float2 a10lo = __half22float2(*reinterpret_cast<__half2*>(&q10.x));
            float2 a10hi = __half22float2(*reinterpret_cast<__half2*>(&q10.y));
            float2 a01lo = __half22float2(*reinterpret_cast<__half2*>(&q01.x));
            float2 a01hi = __half22float2(*reinterpret_cast<__half2*>(&q01.y));
            float2 a11lo = __half22float2(*reinterpret_cast<__half2*>(&q11.x));
            float2 a11hi = __half22float2(*reinterpret_cast<__half2*>(&q11.y));
            pacc += d.x*(w00*a00lo.x + w10*a10lo.x + w01*a01lo.x + w11*a11lo.x);
            pacc += d.y*(w00*a00lo.y + w10*a10lo.y + w01*a01lo.y + w11*a11lo.y);
            pacc += d.z*(w00*a00hi.x + w10*a10hi.x + w01*a01hi.x + w11*a11hi.x);
            pacc += d.w*(w00*a00hi.y + w10*a10hi.y + w01*a01hi.y + w11*a11hi.y);
        }
        #pragma unroll
        for (int o = 16; o; o >>= 1) pacc += __shfl_xor_sync(0xffffffffu, pacc, o);
        if (tx == 0) s_pos[px] = pacc;
    }

    // ---- phase 3: rand dots, 2 pixels/lane, 4 k's/warp, f32x2 FMA ----
    {
        const ulonglong2* dA = reinterpret_cast<const ulonglong2*>(s_dep2 + tx*DSTR);
        const ulonglong2* dB = reinterpret_cast<const ulonglong2*>(s_dep2 + (tx+32)*DSTR);
        const ulonglong2* rp0 = reinterpret_cast<const ulonglong2*>(s_rand + (ty*4+0)*CC);
        const ulonglong2* rp1 = reinterpret_cast<const ulonglong2*>(s_rand + (ty*4+1)*CC);
        const ulonglong2* rp2 = reinterpret_cast<const ulonglong2*>(s_rand + (ty*4+2)*CC);
        const ulonglong2* rp3 = reinterpret_cast<const ulonglong2*>(s_rand + (ty*4+3)*CC);
        u64 aA0=0, aA1=0, aA2=0, aA3=0;
        u64 aB0=0, aB1=0, aB2=0, aB3=0;
        #pragma unroll 8
        for (int c4 = 0; c4 < 64; c4++) {
            ulonglong2 da = dA[c4];
            ulonglong2 db = dB[c4];
            ulonglong2 r0 = rp0[c4], r1 = rp1[c4], r2 = rp2[c4], r3 = rp3[c4];
            aA0 = fma2(da.x, r0.x, aA0); aA0 = fma2(da.y, r0.y, aA0);
            aA1 = fma2(da.x, r1.x, aA1); aA1 = fma2(da.y, r1.y, aA1);
            aA2 = fma2(da.x, r2.x, aA2); aA2 = fma2(da.y, r2.y, aA2);
            aA3 = fma2(da.x, r3.x, aA3); aA3 = fma2(da.y, r3.y, aA3);
            aB0 = fma2(db.x, r0.x, aB0); aB0 = fma2(db.y, r0.y, aB0);
            aB1 = fma2(db.x, r1.x, aB1); aB1 = fma2(db.y, r1.y, aB1);
            aB2 = fma2(db.x, r2.x, aB2); aB2 = fma2(db.y, r2.y, aB2);
            aB3 = fma2(db.x, r3.x, aB3); aB3 = fma2(db.y, r3.y, aB3);
        }
        float2 f;
        f = unpack2(aA0); s_sim[(ty*4+0)*65 + tx]      = f.x + f.y;
        f = unpack2(aA1); s_sim[(ty*4+1)*65 + tx]      = f.x + f.y;
        f = unpack2(aA2); s_sim[(ty*4+2)*65 + tx]      = f.x + f.y;
        f = unpack2(aA3); s_sim[(ty*4+3)*65 + tx]      = f.x + f.y;
        f = unpack2(aB0); s_sim[(ty*4+0)*65 + tx + 32] = f.x + f.y;
        f = unpack2(aB1); s_sim[(ty*4+1)*65 + tx + 32] = f.x + f.y;
        f = unpack2(aB2); s_sim[(ty*4+2)*65 + tx + 32] = f.x + f.y;
        f = unpack2(aB3); s_sim[(ty*4+3)*65 + tx + 32] = f.x + f.y;
    }
    __syncthreads();

    // ---- grid-point dep dump (normalized * TEMP_INV) ----
    {
        int v_row = n0 / WW;
        int u0 = n0 % WW;
        if ((v_row & 7) == 0) {
            int px = ty*8;   // u%8==0 positions within the 64-px tile
            int p = ((v_row >> 3) << 4) + ((u0 + px) >> 3);
            float sc = s_inv[px] * TEMP_INV;
            float* dst = g_depGrid + (b*NPOS + p)*CC;
            #pragma unroll
            for (int jj = 0; jj < 8; jj++) {
                int c = tx + jj*32;
                dst[c] = s_dep2[px*DSTR + c] * sc;
            }
        }
    }

    // ---- phase 4: per-pixel logsumexp / max, lane-parallel over negatives ----
    #pragma unroll
    for (int q = 0; q < 8; q++) {
        int px = ty*8 + q;
        float scale = s_inv[px] * TEMP_INV;
        float pos = s_pos[px] * scale;
        float v = s_sim[tx*65 + px] * scale;
        float mneg = v;
        #pragma unroll
        for (int o = 16; o; o >>= 1) mneg = fmaxf(mneg, __shfl_xor_sync(0xffffffffu, mneg, o));
        float m = fmaxf(pos, mneg);
        float e = expf(v - m);
        #pragma unroll
        for (int o = 16; o; o >>= 1) e += __shfl_xor_sync(0xffffffffu, e, o);
        if (tx == 0) {
            int gp = b*NN + n0 + px;
            g_pos[gp]    = pos;
            g_lse[gp]    = m + logf(e + expf(pos - m));
            g_maxneg[gp] = mneg;
        }
    }
}

// ---------------- kernel 3: hard negatives (dep pre-normalized) --------------
__global__ __launch_bounds__(256) void k_hard(const float* __restrict__ proj,
                                              const int*   __restrict__ offu,
                                              const int*   __restrict__ offv) {
    __shared__ float s_depv[CC];
    __shared__ float s_hsim[NHARD];
    const int tid = threadIdx.x;
    const int tx = tid & 31;
    const int ty = tid >> 5;
    const int b = blockIdx.x >> 8;
    const int p = blockIdx.x & 255;
    const int gh = (p >> 4) * 8;
    const int gw = (p & 15) * 8;
    const int ng = gh*WW + gw;

    s_depv[tid] = g_depGrid[(b*NPOS + p)*CC + tid];
    __syncthreads();

    float pu = proj[b*2*NN + ng];
    float pv = proj[b*2*NN + NN + ng];
    int posu = (int)fminf(fmaxf(pu, 0.0f), (float)(WW-1));
    int posv = (int)fminf(fmaxf(pv, 0.0f), (float)(HH-1));

    const float4* dv = reinterpret_cast<const float4*>(s_depv);
    #pragma unroll
    for (int g3 = 0; g3 < 3; g3++) {
        int hbase = ty*12 + g3*4;
        const uint4* r[4];
        #pragma unroll
        for (int j = 0; j < 4; j++) {
            int h = hbase + j;
            int ou = offu[(b*NHARD + h)*NPOS + p];
            int ov = offv[(b*NHARD + h)*NPOS + p];
            if (ou == 0 && ov == 0) ou = 1;
            int hu = min(max(posu + ou, 0), WW-1);
            int hv = min(max(posv + ov, 0), HH-1);
            r[j] = reinterpret_cast<const uint4*>(g_rgbTh + (size_t)(b*NN + hv*WW + hu)*CC);
        }
        // lane tx owns channels 8tx..8tx+7 (one uint4 = 8 halves per row)
        float4 d0 = dv[2*tx];
        float4 d1 = dv[2*tx + 1];
        float acc[4];
        #pragma unroll
        for (int j = 0; j < 4; j++) {
            uint4 q = r[j][tx];
            float2 f0 = __half22float2(*reinterpret_cast<__half2*>(&q.x));
            float2 f1 = __half22float2(*reinterpret_cast<__half2*>(&q.y));
            float2 f2 = __half22float2(*reinterpret_cast<__half2*>(&q.z));
            float2 f3 = __half22float2(*reinterpret_cast<__half2*>(&q.w));
            float a = 0.0f;
            a += d0.x*f0.x; a += d0.y*f0.y; a += d0.z*f1.x; a += d0.w*f1.y;
            a += d1.x*f2.x; a += d1.y*f2.y; a += d1.z*f3.x; a += d1.w*f3.y;
            acc[j] = a;
        }
        #pragma unroll
        for (int o = 16; o; o >>= 1) {
            acc[0] += __shfl_xor_sync(0xffffffffu, acc[0], o);
            acc[1] += __shfl_xor_sync(0xffffffffu, acc[1], o);
            acc[2] += __shfl_xor_sync(0xffffffffu, acc[2], o);
            acc[3] += __shfl_xor_sync(0xffffffffu, acc[3], o);
        }
        if (tx == 0) {
            s_hsim[hbase+0] = acc[0];
            s_hsim[hbase+1] = acc[1];
            s_hsim[hbase+2] = acc[2];
            s_hsim[hbase+3] = acc[3];
        }
    }
    __syncthreads();

    if (tid < 32) {
        float v0 = s_hsim[tx];
        float v1 = s_hsim[tx + 32];
        float v2 = s_hsim[tx + 64];
        float m = fmaxf(fmaxf(v0, v1), v2);
        #pragma unroll
        for (int o = 16; o; o >>= 1) m = fmaxf(m, __shfl_xor_sync(0xffffffffu, m, o));
        float se = expf(v0 - m) + expf(v1 - m) + expf(v2 - m);
        #pragma unroll
        for (int o = 16; o; o >>= 1) se += __shfl_xor_sync(0xffffffffu, se, o);
        if (tx == 0) {
            g_lse_hard[b*NPOS + p] = m + logf(se);
            g_max_hard[b*NPOS + p] = m;
        }
    }
}

// ---------------- kernel 4: loss/accuracy reduction ---------------------------
__global__ __launch_bounds__(256) void k_loss(const float* __restrict__ valid) {
    __shared__ float sA[8], sB[8], sC[8];
    const int g = blockIdx.x * 256 + threadIdx.x;
    const int b = g >> 14;
    const int n = g & (NN-1);
    const int vq = n >> 7;
    const int u  = n & 127;

    float lse = g_lse[g];
    float pos = g_pos[g];
    float mx  = g_maxneg[g];
    if (((vq & 7) == 0) && ((u & 7) == 0)) {
        int p = (vq >> 3) * 16 + (u >> 3);
        float lh = g_lse_hard[b*NPOS + p];
        float mh = g_max_hard[b*NPOS + p];
        float m = fmaxf(lse, lh);
        lse = m + logf(expf(lse - m) + expf(lh - m));
        mx = fmaxf(mx, mh);
    }
    float mask = valid[g];
    float lossp = (lse - pos) * mask;
    float corr = (pos > mx && mask > 0.5f) ? 1.0f : 0.0f;
    float mk = mask;

    #pragma unroll
    for (int o = 16; o; o >>= 1) {
        lossp += __shfl_xor_sync(0xffffffffu, lossp, o);
        mk    += __shfl_xor_sync(0xffffffffu, mk,    o);
        corr  += __shfl_xor_sync(0xffffffffu, corr,  o);
    }
    if ((threadIdx.x & 31) == 0) {
        sA[threadIdx.x >> 5] = lossp;
        sB[threadIdx.x >> 5] = mk;
        sC[threadIdx.x >> 5] = corr;
    }
    __syncthreads();
    if (threadIdx.x == 0) {
        float a = 0.f, bb2 = 0.f, c2 = 0.f;
        #pragma unroll
        for (int j = 0; j < 8; j++) { a += sA[j]; bb2 += sB[j]; c2 += sC[j]; }
        atomicAdd(&g_acc[0], a);
        atomicAdd(&g_acc[1], bb2);
        atomicAdd(&g_acc[2], c2);
    }
}

// ---------------- kernel 5: epilogue ------------------------------------------
__global__ void k_out(float* out) {
    float denom = fmaxf(g_acc[1], 1.0f);
    out[0] = g_acc[0] / denom;
    out[1] = g_acc[2] / denom * 100.0f;
}

// ---------------- launch -------------------------------------------------------
extern "C" void kernel_launch(void* const* d_in, const int* in_sizes, int n_in,
                              void* d_out, int out_size) {
    const float* rgb   = (const float*)d_in[0];
    const float* dep   = (const float*)d_in[1];
    const float* proj  = (const float*)d_in[2];
    const float* valid = (const float*)d_in[3];
    const int*   ridx  = (const int*)d_in[4];
    const int*   offu  = (const int*)d_in[5];
    const int*   offv  = (const int*)d_in[6];
    float* out = (float*)d_out;

    const int smem_main = (64*DSTR + NRAND*CC + NRAND*65 + 64 + 64 + 4*65) * (int)sizeof(float);
    cudaFuncSetAttribute(k_main, cudaFuncAttributeMaxDynamicSharedMemorySize, smem_main);

    k_norm_t<<<BB*NN/32, 256>>>(rgb);
    k_main<<<BB*NN/64, 256, smem_main>>>(dep, proj, ridx);
    k_hard<<<BB*NPOS, 256>>>(proj, offu, offv);
    k_loss<<<BB*NN/256, 256>>>(valid);
    k_out<<<1, 1>>>(out);
}

// round 8
// speedup vs baseline: 2.1033x; 1.2683x over previous
#include <cuda_runtime.h>
#include <cuda_fp16.h>
#include <math.h>

#define BB 8
#define CC 256
#define HH 128
#define WW 128
#define NN (HH*WW)          // 16384
#define NPOS 256
#define NHARD 96
#define NRAND 32
#define TEMP_INV (1.0f/0.07f)

#define ROWQ 33             // quads (16B units) per padded fp16 row (264 halves)

// ---------------- scratch (static device globals; no allocation) ------------
__device__ __half g_rgbTh[BB*NN*CC];    // normalized rgb (fp16), [b][px][ch]
__device__ float g_depGrid[BB*NPOS*CC]; // normalized*TEMP_INV dep at grid pts
__device__ float g_pos[BB*NN];
__device__ float g_lse[BB*NN];
__device__ float g_maxneg[BB*NN];
__device__ float g_lse_hard[BB*NPOS];
__device__ float g_max_hard[BB*NPOS];
__device__ float g_acc[3];              // loss_sum, mask_sum, correct_sum
__device__ unsigned g_done;

// ---------------- mma/ldmatrix helpers ---------------------------------------
__device__ __forceinline__ void ldmx4(unsigned* r, unsigned addr) {
    asm volatile("ldmatrix.sync.aligned.m8n8.x4.shared.b16 {%0,%1,%2,%3}, [%4];"
                 : "=r"(r[0]), "=r"(r[1]), "=r"(r[2]), "=r"(r[3]) : "r"(addr));
}
__device__ __forceinline__ void ldmx2(unsigned* r, unsigned addr) {
    asm volatile("ldmatrix.sync.aligned.m8n8.x2.shared.b16 {%0,%1}, [%2];"
                 : "=r"(r[0]), "=r"(r[1]) : "r"(addr));
}
__device__ __forceinline__ void mma16816(float* d, const unsigned* a, const unsigned* b) {
    asm volatile(
        "mma.sync.aligned.m16n8k16.row.col.f32.f16.f16.f32 "
        "{%0,%1,%2,%3}, {%4,%5,%6,%7}, {%8,%9}, {%0,%1,%2,%3};"
        : "+f"(d[0]), "+f"(d[1]), "+f"(d[2]), "+f"(d[3])
        : "r"(a[0]), "r"(a[1]), "r"(a[2]), "r"(a[3]),
          "r"(b[0]), "r"(b[1]));
}

// ---------------- kernel 1: normalize + transpose rgb -> g_rgbTh -------------
__global__ __launch_bounds__(256) void k_norm_t(const float* __restrict__ in) {
    __shared__ float s_tile[CC*33];
    __shared__ float s_red[8*33];
    __shared__ float s_inv[32];
    const int tid = threadIdx.x;
    const int tx = tid & 31;        // pixel in tile
    const int ty = tid >> 5;        // channel group
    const int blocksPerBatch = NN/32;
    const int b  = blockIdx.x / blocksPerBatch;
    const int n0 = (blockIdx.x % blocksPerBatch) * 32;

    if (blockIdx.x == 0 && tid < 3) g_acc[tid] = 0.0f;
    if (blockIdx.x == 0 && tid == 3) g_done = 0;

    const float* src = in + b*CC*NN + n0;
    #pragma unroll 8
    for (int i = 0; i < 32; i++) {
        int c = i*8 + ty;
        s_tile[c*33 + tx] = src[c*NN + tx];
    }
    __syncthreads();

    float ss = 0.0f;
    #pragma unroll
    for (int j = 0; j < 32; j++) {
        float v = s_tile[(ty*32 + j)*33 + tx];
        ss += v*v;
    }
    s_red[ty*33 + tx] = ss;
    __syncthreads();
    if (ty == 0) {
        float t = 0.0f;
        #pragma unroll
        for (int j = 0; j < 8; j++) t += s_red[j*33 + tx];
        s_inv[tx] = 1.0f / fmaxf(sqrtf(t), 1e-12f);
    }
    __syncthreads();

    __half* dst = g_rgbTh + (size_t)(b*NN + n0)*CC;
    const int cb = tid & 31;        // chunk 0..31 (channels cb*8..cb*8+7)
    const int pq = tid >> 5;        // pixel sub-index 0..7
    #pragma unroll
    for (int it = 0; it < 4; it++) {
        int px = it*8 + pq;
        float inv = s_inv[px];
        float v[8];
        #pragma unroll
        for (int j = 0; j < 8; j++) v[j] = s_tile[(cb*8+j)*33 + px] * inv;
        uint4 q;
        __half2 h;
        h = __floats2half2_rn(v[0], v[1]); q.x = *reinterpret_cast<unsigned*>(&h);
        h = __floats2half2_rn(v[2], v[3]); q.y = *reinterpret_cast<unsigned*>(&h);
        h = __floats2half2_rn(v[4], v[5]); q.z = *reinterpret_cast<unsigned*>(&h);
        h = __floats2half2_rn(v[6], v[7]); q.w = *reinterpret_cast<unsigned*>(&h);
        reinterpret_cast<uint4*>(dst + (size_t)px*CC)[cb] = q;
    }
}

// ---------------- kernel 2: main pass, split-precision dep + tensor GEMM -----
__device__ __forceinline__ int corner_idx(int xx, int yy, float& w) {
    bool v = (xx >= 0) & (xx < WW) & (yy >= 0) & (yy < HH);
    if (!v) w = 0.0f;
    int cx = min(max(xx, 0), WW-1);
    int cy = min(max(yy, 0), HH-1);
    return cy*WW + cx;
}

__global__ __launch_bounds__(256) void k_main(const float* __restrict__ dep,
                                              const float* __restrict__ proj,
                                              const int*   __restrict__ rand_idx) {
    extern __shared__ float sm[];
    __half* s_depH  = reinterpret_cast<__half*>(sm);     // hi: 64*264 halves
    __half* s_depL  = s_depH + 64*ROWQ*8;                // lo: 64*264 halves
    __half* s_randH = s_depL + 64*ROWQ*8;                // 32*264 halves
    float*  s_sim   = reinterpret_cast<float*>(s_randH + 32*ROWQ*8); // 32*65
    float*  s_pos   = s_sim + NRAND*65;                  // 64
    float*  s_inv   = s_pos + 64;                        // 64
    float*  s_red   = s_inv + 64;                        // 4*65

    const int tid = threadIdx.x;
    const int tx  = tid & 31;
    const int ty  = tid >> 5;                  // warp id 0..7
    const int blocksPerBatch = NN/64;
    const int b  = blockIdx.x / blocksPerBatch;
    const int n0 = (blockIdx.x % blocksPerBatch) * 64;

    // ---- stage dep tile split fp16 hi/lo + partial norms (fp32) ----
    {
        const int px = tid & 63;               // pixel 0..63
        const int cg = tid >> 6;               // 0..3 -> chunks cg*8..cg*8+7
        const float* dsrc = dep + b*CC*NN + n0 + px;
        float ss = 0.0f;
        uint4* hrow = reinterpret_cast<uint4*>(s_depH) + px*ROWQ;
        uint4* lrow = reinterpret_cast<uint4*>(s_depL) + px*ROWQ;
        #pragma unroll
        for (int j = 0; j < 8; j++) {
            int chunk = cg*8 + j;
            float v[8];
            __half hi[8], lo[8];
            #pragma unroll
            for (int t = 0; t < 8; t++) {
                v[t] = dsrc[(chunk*8 + t)*NN];
                ss += v[t]*v[t];
                hi[t] = __float2half_rn(v[t]);
                lo[t] = __float2half_rn(v[t] - __half2float(hi[t]));
            }
            uint4 qh, ql;
            __half2 h;
            h = __halves2half2(hi[0], hi[1]); qh.x = *reinterpret_cast<unsigned*>(&h);
            h = __halves2half2(hi[2], hi[3]); qh.y = *reinterpret_cast<unsigned*>(&h);
            h = __halves2half2(hi[4], hi[5]); qh.z = *reinterpret_cast<unsigned*>(&h);
            h = __halves2half2(hi[6], hi[7]); qh.w = *reinterpret_cast<unsigned*>(&h);
            h = __halves2half2(lo[0], lo[1]); ql.x = *reinterpret_cast<unsigned*>(&h);
            h = __halves2half2(lo[2], lo[3]); ql.y = *reinterpret_cast<unsigned*>(&h);
            h = __halves2half2(lo[4], lo[5]); ql.z = *reinterpret_cast<unsigned*>(&h);
            h = __halves2half2(lo[6], lo[7]); ql.w = *reinterpret_cast<unsigned*>(&h);
            hrow[chunk] = qh;
            lrow[chunk] = ql;
        }
        s_red[cg*65 + px] = ss;
    }
    // ---- stage rand vectors (fp16 rows, padded) ----
    {
        int k = tid >> 3, part = tid & 7;
        int ridx = rand_idx[b*NRAND + k];
        const uint4* row = reinterpret_cast<const uint4*>(g_rgbTh + (size_t)(b*NN + ridx)*CC);
        uint4* drow = reinterpret_cast<uint4*>(s_randH) + k*ROWQ;
        #pragma unroll
        for (int i = 0; i < 4; i++) {
            int chunk = part + 8*i;
            drow[chunk] = row[chunk];
        }
    }
    __syncthreads();
    if (tid < 64) {
        float t = s_red[tid] + s_red[65 + tid] + s_red[2*65 + tid] + s_red[3*65 + tid];
        s_inv[tid] = 1.0f / fmaxf(sqrtf(t), 1e-12f);
    }
    __syncthreads();

    // ---- phase 3: rand GEMM on tensor cores, hi+lo split dep ----
    {
        unsigned aHBase = (unsigned)__cvta_generic_to_shared(s_depH);
        unsigned aLBase = (unsigned)__cvta_generic_to_shared(s_depL);
        unsigned bBase  = (unsigned)__cvta_generic_to_shared(s_randH);
        const int pxb = (ty & 3) * 16;
        const int kb0 = (ty >> 2) * 16;
        const unsigned aRow = (unsigned)(pxb + (tx & 15)) * ROWQ + (unsigned)(tx >> 4);
        const unsigned bRow0 = (unsigned)(kb0 + (tx & 7)) * ROWQ + (unsigned)((tx >> 3) & 1);
        const unsigned bRow1 = bRow0 + 8u*ROWQ;
        float d0[4] = {0,0,0,0}, d1[4] = {0,0,0,0};
        #pragma unroll
        for (int kk = 0; kk < 16; kk++) {
            unsigned ah[4], al[4], b0r[2], b1r[2];
            ldmx4(ah,  aHBase + (aRow  + 2*kk) * 16);
            ldmx4(al,  aLBase + (aRow  + 2*kk) * 16);
            ldmx2(b0r, bBase  + (bRow0 + 2*kk) * 16);
            ldmx2(b1r, bBase  + (bRow1 + 2*kk) * 16);
            mma16816(d0, ah, b0r);
            mma16816(d0, al, b0r);
            mma16816(d1, ah, b1r);
            mma16816(d1, al, b1r);
        }
        int pxl = pxb + (tx >> 2);
        int kl  = (tx & 3) * 2;
        s_sim[(kb0 + kl + 0)*65 + pxl]     = d0[0];
        s_sim[(kb0 + kl + 1)*65 + pxl]     = d0[1];
        s_sim[(kb0 + kl + 0)*65 + pxl + 8] = d0[2];
        s_sim[(kb0 + kl + 1)*65 + pxl + 8] = d0[3];
        s_sim[(kb0 + 8 + kl + 0)*65 + pxl]     = d1[0];
        s_sim[(kb0 + 8 + kl + 1)*65 + pxl]     = d1[1];
        s_sim[(kb0 + 8 + kl + 0)*65 + pxl + 8] = d1[2];
        s_sim[(kb0 + 8 + kl + 1)*65 + pxl + 8] = d1[3];
    }

    // ---- phase 2: pos_sim (warp handles 8 pixels), dep = hi + lo ----
    const float* projU = proj + b*2*NN;
    const float* projV = projU + NN;
    const uint4* depHQ = reinterpret_cast<const uint4*>(s_depH);
    const uint4* depLQ = reinterpret_cast<const uint4*>(s_depL);
    #pragma unroll
    for (int q = 0; q < 8; q++) {
        int px = ty*8 + q;
        int n  = n0 + px;
        float pu = projU[n], pv = projV[n];
        float x0f = floorf(pu), y0f = floorf(pv);
        float wx = pu - x0f, wy = pv - y0f;
        int x0 = (int)x0f, y0 = (int)y0f;
        float w00 = (1.0f-wx)*(1.0f-wy), w10 = wx*(1.0f-wy);
        float w01 = (1.0f-wx)*wy,        w11 = wx*wy;
        int i00 = corner_idx(x0,   y0,   w00);
        int i10 = corner_idx(x0+1, y0,   w10);
        int i01 = corner_idx(x0,   y0+1, w01);
        int i11 = corner_idx(x0+1, y0+1, w11);
        const uint4* r00 = reinterpret_cast<const uint4*>(g_rgbTh + (size_t)(b*NN + i00)*CC);
        const uint4* r10 = reinterpret_cast<const uint4*>(g_rgbTh + (size_t)(b*NN + i10)*CC);
        const uint4* r01 = reinterpret_cast<const uint4*>(g_rgbTh + (size_t)(b*NN + i01)*CC);
        const uint4* r11 = reinterpret_cast<const uint4*>(g_rgbTh + (size_t)(b*NN + i11)*CC);
        uint4 dqh = depHQ[px*ROWQ + tx];
        uint4 dql = depLQ[px*ROWQ + tx];
        uint4 q00 = r00[tx], q10 = r10[tx], q01 = r01[tx], q11 = r11[tx];
        float pacc = 0.0f;
        const unsigned* duh = &dqh.x;
        const unsigned* dul = &dql.x;
        const unsigned* u00 = &q00.x;
        const unsigned* u10 = &q10.x;
        const unsigned* u01 = &q01.x;
        const unsigned* u11 = &q11.x;
        #pragma unroll
        for (int j = 0; j < 4; j++) {
            float2 dh = __half22float2(*reinterpret_cast<const __half2*>(&duh[j]));
            float2 dl = __half22float2(*reinterpret_cast<const __half2*>(&dul[j]));
            float dx = dh.x + dl.x, dy = dh.y + dl.y;
            float2 a00 = __half22float2(*reinterpret_cast<const __half2*>(&u00[j]));
            float2 a10 = __half22float2(*reinterpret_cast<const __half2*>(&u10[j]));
            float2 a01 = __half22float2(*reinterpret_cast<const __half2*>(&u01[j]));
            float2 a11 = __half22float2(*reinterpret_cast<const __half2*>(&u11[j]));
            pacc += dx*(w00*a00.x + w10*a10.x + w01*a01.x + w11*a11.x);
            pacc += dy*(w00*a00.y + w10*a10.y + w01*a01.y + w11*a11.y);
        }
        #pragma unroll
        for (int o = 16; o; o >>= 1) pacc += __shfl_xor_sync(0xffffffffu, pacc, o);
        if (tx == 0) s_pos[px] = pacc;
    }

    // ---- grid-point dep dump (hi+lo -> fp32, normalized * TEMP_INV) ----
    {
        int v_row = n0 / WW;
        int u0 = n0 % WW;
        if ((v_row & 7) == 0) {
            int px = ty*8;   // u%8==0 positions within the 64-px tile
            int p = ((v_row >> 3) << 4) + ((u0 + px) >> 3);
            float sc = s_inv[px] * TEMP_INV;
            float* dst = g_depGrid + (b*NPOS + p)*CC;
            uint4 dqh = depHQ[px*ROWQ + tx];
            uint4 dql = depLQ[px*ROWQ + tx];
            const unsigned* duh = &dqh.x;
            const unsigned* dul = &dql.x;
            float4 o0, o1;
            float2 fh, fl;
            fh = __half22float2(*reinterpret_cast<const __half2*>(&duh[0]));
            fl = __half22float2(*reinterpret_cast<const __half2*>(&dul[0]));
            o0.x = (fh.x+fl.x)*sc; o0.y = (fh.y+fl.y)*sc;
            fh = __half22float2(*reinterpret_cast<const __half2*>(&duh[1]));
            fl = __half22float2(*reinterpret_cast<const __half2*>(&dul[1]));
            o0.z = (fh.x+fl.x)*sc; o0.w = (fh.y+fl.y)*sc;
            fh = __half22float2(*reinterpret_cast<const __half2*>(&duh[2]));
            fl = __half22float2(*reinterpret_cast<const __half2*>(&dul[2]));
            o1.x = (fh.x+fl.x)*sc; o1.y = (fh.y+fl.y)*sc;
            fh = __half22float2(*reinterpret_cast<const __half2*>(&duh[3]));
            fl = __half22float2(*reinterpret_cast<const __half2*>(&dul[3]));
            o1.z = (fh.x+fl.x)*sc; o1.w = (fh.y+fl.y)*sc;
            reinterpret_cast<float4*>(dst + tx*8)[0] = o0;
            reinterpret_cast<float4*>(dst + tx*8)[1] = o1;
        }
    }
    __syncthreads();

    // ---- phase 4: per-pixel logsumexp / max, lane-parallel over negatives ----
    #pragma unroll
    for (int q = 0; q < 8; q++) {
        int px = ty*8 + q;
        float scale = s_inv[px] * TEMP_INV;
        float pos = s_pos[px] * scale;
        float v = s_sim[tx*65 + px] * scale;
        float mneg = v;
        #pragma unroll
        for (int o = 16; o; o >>= 1) mneg = fmaxf(mneg, __shfl_xor_sync(0xffffffffu, mneg, o));
        float m = fmaxf(pos, mneg);
        float e = expf(v - m);
        #pragma unroll
        for (int o = 16; o; o >>= 1) e += __shfl_xor_sync(0xffffffffu, e, o);
        if (tx == 0) {
            int gp = b*NN + n0 + px;
            g_pos[gp]    = pos;
            g_lse[gp]    = m + logf(e + expf(pos - m));
            g_maxneg[gp] = mneg;
        }
    }
}

// ---------------- kernel 3: hard negatives (dep pre-normalized) --------------
__global__ __launch_bounds__(256) void k_hard(const float* __restrict__ proj,
                                              const int*   __restrict__ offu,
                                              const int*   __restrict__ offv) {
    __shared__ float s_depv[CC];
    __shared__ float s_hsim[NHARD];
    const int tid = threadIdx.x;
    const int tx = tid & 31;
    const int ty = tid >> 5;
    const int b = blockIdx.x >> 8;
    const int p = blockIdx.x & 255;
    const int gh = (p >> 4) * 8;
    const int gw = (p & 15) * 8;
    const int ng = gh*WW + gw;

    s_depv[tid] = g_depGrid[(b*NPOS + p)*CC + tid];
    __syncthreads();

    float pu = proj[b*2*NN + ng];
    float pv = proj[b*2*NN + NN + ng];
    int posu = (int)fminf(fmaxf(pu, 0.0f), (float)(WW-1));
    int posv = (int)fminf(fmaxf(pv, 0.0f), (float)(HH-1));

    const float4* dv = reinterpret_cast<const float4*>(s_depv);
    #pragma unroll
    for (int g3 = 0; g3 < 3; g3++) {
        int hbase = ty*12 + g3*4;
        const uint4* r[4];
        #pragma unroll
        for (int j = 0; j < 4; j++) {
            int h = hbase + j;
            int ou = offu[(b*NHARD + h)*NPOS + p];
            int ov = offv[(b*NHARD + h)*NPOS + p];
            if (ou == 0 && ov == 0) ou = 1;
            int hu = min(max(posu + ou, 0), WW-1);
            int hv = min(max(posv + ov, 0), HH-1);
            r[j] = reinterpret_cast<const uint4*>(g_rgbTh + (size_t)(b*NN + hv*WW + hu)*CC);
        }
        float4 d0 = dv[2*tx];
        float4 d1 = dv[2*tx + 1];
        float acc[4];
        #pragma unroll
        for (int j = 0; j < 4; j++) {
            uint4 q = r[j][tx];
            float2 f0 = __half22float2(*reinterpret_cast<__half2*>(&q.x));
            float2 f1 = __half22float2(*reinterpret_cast<__half2*>(&q.y));
            float2 f2 = __half22float2(*reinterpret_cast<__half2*>(&q.z));
            float2 f3 = __half22float2(*reinterpret_cast<__half2*>(&q.w));
            float a = 0.0f;
            a += d0.x*f0.x; a += d0.y*f0.y; a += d0.z*f1.x; a += d0.w*f1.y;
            a += d1.x*f2.x; a += d1.y*f2.y; a += d1.z*f3.x; a += d1.w*f3.y;
            acc[j] = a;
        }
        #pragma unroll
        for (int o = 16; o; o >>= 1) {
            acc[0] += __shfl_xor_sync(0xffffffffu, acc[0], o);
            acc[1] += __shfl_xor_sync(0xffffffffu, acc[1], o);
            acc[2] += __shfl_xor_sync(0xffffffffu, acc[2], o);
            acc[3] += __shfl_xor_sync(0xffffffffu, acc[3], o);
        }
        if (tx == 0) {
            s_hsim[hbase+0] = acc[0];
            s_hsim[hbase+1] = acc[1];
            s_hsim[hbase+2] = acc[2];
            s_hsim[hbase+3] = acc[3];
        }
    }
    __syncthreads();

    if (tid < 32) {
        float v0 = s_hsim[tx];
        float v1 = s_hsim[tx + 32];
        float v2 = s_hsim[tx + 64];
        float m = fmaxf(fmaxf(v0, v1), v2);
        #pragma unroll
        for (int o = 16; o; o >>= 1) m = fmaxf(m, __shfl_xor_sync(0xffffffffu, m, o));
        float se = expf(v0 - m) + expf(v1 - m) + expf(v2 - m);
        #pragma unroll
        for (int o = 16; o; o >>= 1) se += __shfl_xor_sync(0xffffffffu, se, o);
        if (tx == 0) {
            g_lse_hard[b*NPOS + p] = m + logf(se);
            g_max_hard[b*NPOS + p] = m;
        }
    }
}

// ---------------- kernel 4: loss/accuracy reduction + fused epilogue ---------
__global__ __launch_bounds__(256) void k_loss(const float* __restrict__ valid,
                                              float* __restrict__ out) {
    __shared__ float sA[8], sB[8], sC[8];
    const int g = blockIdx.x * 256 + threadIdx.x;
    const int b = g >> 14;
    const int n = g & (NN-1);
    const int vq = n >> 7;
    const int u  = n & 127;

    float lse = g_lse[g];
    float pos = g_pos[g];
    float mx  = g_maxneg[g];
    if (((vq & 7) == 0) && ((u & 7) == 0)) {
        int p = (vq >> 3) * 16 + (u >> 3);
        float lh = g_lse_hard[b*NPOS + p];
        float mh = g_max_hard[b*NPOS + p];
        float m = fmaxf(lse, lh);
        lse = m + logf(expf(lse - m) + expf(lh - m));
        mx = fmaxf(mx, mh);
    }
    float mask = valid[g];
    float lossp = (lse - pos) * mask;
    float corr = (pos > mx && mask > 0.5f) ? 1.0f : 0.0f;
    float mk = mask;

    #pragma unroll
    for (int o = 16; o; o >>= 1) {
        lossp += __shfl_xor_sync(0xffffffffu, lossp, o);
        mk    += __shfl_xor_sync(0xffffffffu, mk,    o);
        corr  += __shfl_xor_sync(0xffffffffu, corr,  o);
    }
    if ((threadIdx.x & 31) == 0) {
        sA[threadIdx.x >> 5] = lossp;
        sB[threadIdx.x >> 5] = mk;
        sC[threadIdx.x >> 5] = corr;
    }
    __syncthreads();
    if (threadIdx.x == 0) {
        float a = 0.f, bb2 = 0.f, c2 = 0.f;
        #pragma unroll
        for (int j = 0; j < 8; j++) { a += sA[j]; bb2 += sB[j]; c2 += sC[j]; }
        atomicAdd(&g_acc[0], a);
        atomicAdd(&g_acc[1], bb2);
        atomicAdd(&g_acc[2], c2);
        __threadfence();
        unsigned t = atomicAdd(&g_done, 1u);
        if (t == gridDim.x - 1) {
            __threadfence();
            float denom = fmaxf(g_acc[1], 1.0f);
            out[0] = g_acc[0] / denom;
            out[1] = g_acc[2] / denom * 100.0f;
        }
    }
}

// ---------------- launch -------------------------------------------------------
extern "C" void kernel_launch(void* const* d_in, const int* in_sizes, int n_in,
                              void* d_out, int out_size) {
    const float* rgb   = (const float*)d_in[0];
    const float* dep   = (const float*)d_in[1];
    const float* proj  = (const float*)d_in[2];
    const float* valid = (const float*)d_in[3];
    const int*   ridx  = (const int*)d_in[4];
    const int*   offu  = (const int*)d_in[5];
    const int*   offv  = (const int*)d_in[6];
    float* out = (float*)d_out;

    const int smem_main = 64*ROWQ*16*2 + 32*ROWQ*16
                        + (NRAND*65 + 64 + 64 + 4*65) * (int)sizeof(float);
    cudaFuncSetAttribute(k_main, cudaFuncAttributeMaxDynamicSharedMemorySize, smem_main);

    k_norm_t<<<BB*NN/32, 256>>>(rgb);
    k_main<<<BB*NN/64, 256, smem_main>>>(dep, proj, ridx);
    k_hard<<<BB*NPOS, 256>>>(proj, offu, offv);
    k_loss<<<BB*NN/256, 256>>>(valid, out);
}

// round 9
// speedup vs baseline: 2.1334x; 1.0143x over previous
#include <cuda_runtime.h>
#include <cuda_fp16.h>
#include <math.h>

#define BB 8
#define CC 256
#define HH 128
#define WW 128
#define NN (HH*WW)          // 16384
#define NPOS 256
#define NHARD 96
#define NRAND 32
#define TEMP_INV (1.0f/0.07f)

#define ROWQ 33             // quads (16B units) per padded fp16 row (264 halves)

// ---------------- scratch (static device globals; no allocation) ------------
__device__ __half g_rgbTh[BB*NN*CC];    // normalized rgb (fp16), [b][px][ch]
__device__ float g_depGrid[BB*NPOS*CC]; // normalized*TEMP_INV dep at grid pts
__device__ float g_posG[BB*NPOS];       // pos_sim at grid points
__device__ float g_lseG[BB*NPOS];       // base lse at grid points
__device__ float g_mxG[BB*NPOS];        // rand max at grid points
__device__ float g_acc[3];              // loss_sum, mask_sum, correct_sum
__device__ unsigned g_done;

// ---------------- mma/ldmatrix helpers ---------------------------------------
__device__ __forceinline__ void ldmx4(unsigned* r, unsigned addr) {
    asm volatile("ldmatrix.sync.aligned.m8n8.x4.shared.b16 {%0,%1,%2,%3}, [%4];"
                 : "=r"(r[0]), "=r"(r[1]), "=r"(r[2]), "=r"(r[3]) : "r"(addr));
}
__device__ __forceinline__ void ldmx2(unsigned* r, unsigned addr) {
    asm volatile("ldmatrix.sync.aligned.m8n8.x2.shared.b16 {%0,%1}, [%2];"
                 : "=r"(r[0]), "=r"(r[1]) : "r"(addr));
}
__device__ __forceinline__ void mma16816(float* d, const unsigned* a, const unsigned* b) {
    asm volatile(
        "mma.sync.aligned.m16n8k16.row.col.f32.f16.f16.f32 "
        "{%0,%1,%2,%3}, {%4,%5,%6,%7}, {%8,%9}, {%0,%1,%2,%3};"
        : "+f"(d[0]), "+f"(d[1]), "+f"(d[2]), "+f"(d[3])
        : "r"(a[0]), "r"(a[1]), "r"(a[2]), "r"(a[3]),
          "r"(b[0]), "r"(b[1]));
}

// ---------------- kernel 1: normalize + transpose rgb -> g_rgbTh -------------
__global__ __launch_bounds__(256) void k_norm_t(const float* __restrict__ in) {
    __shared__ float s_tile[CC*33];
    __shared__ float s_red[8*33];
    __shared__ float s_inv[32];
    const int tid = threadIdx.x;
    const int tx = tid & 31;        // pixel in tile
    const int ty = tid >> 5;        // channel group
    const int blocksPerBatch = NN/32;
    const int b  = blockIdx.x / blocksPerBatch;
    const int n0 = (blockIdx.x % blocksPerBatch) * 32;

    if (blockIdx.x == 0 && tid < 3) g_acc[tid] = 0.0f;
    if (blockIdx.x == 0 && tid == 3) g_done = 0;

    const float* src = in + b*CC*NN + n0;
    #pragma unroll 8
    for (int i = 0; i < 32; i++) {
        int c = i*8 + ty;
        s_tile[c*33 + tx] = src[c*NN + tx];
    }
    __syncthreads();

    float ss = 0.0f;
    #pragma unroll
    for (int j = 0; j < 32; j++) {
        float v = s_tile[(ty*32 + j)*33 + tx];
        ss += v*v;
    }
    s_red[ty*33 + tx] = ss;
    __syncthreads();
    if (ty == 0) {
        float t = 0.0f;
        #pragma unroll
        for (int j = 0; j < 8; j++) t += s_red[j*33 + tx];
        s_inv[tx] = 1.0f / fmaxf(sqrtf(t), 1e-12f);
    }
    __syncthreads();

    __half* dst = g_rgbTh + (size_t)(b*NN + n0)*CC;
    const int cb = tid & 31;        // chunk 0..31 (channels cb*8..cb*8+7)
    const int pq = tid >> 5;        // pixel sub-index 0..7
    #pragma unroll
    for (int it = 0; it < 4; it++) {
        int px = it*8 + pq;
        float inv = s_inv[px];
        float v[8];
        #pragma unroll
        for (int j = 0; j < 8; j++) v[j] = s_tile[(cb*8+j)*33 + px] * inv;
        uint4 q;
        __half2 h;
        h = __floats2half2_rn(v[0], v[1]); q.x = *reinterpret_cast<unsigned*>(&h);
        h = __floats2half2_rn(v[2], v[3]); q.y = *reinterpret_cast<unsigned*>(&h);
        h = __floats2half2_rn(v[4], v[5]); q.z = *reinterpret_cast<unsigned*>(&h);
        h = __floats2half2_rn(v[6], v[7]); q.w = *reinterpret_cast<unsigned*>(&h);
        reinterpret_cast<uint4*>(dst + (size_t)px*CC)[cb] = q;
    }
}

// ---------------- kernel 2: main pass + fused loss (non-grid pixels) ---------
__device__ __forceinline__ int corner_idx(int xx, int yy, float& w) {
    bool v = (xx >= 0) & (xx < WW) & (yy >= 0) & (yy < HH);
    if (!v) w = 0.0f;
    int cx = min(max(xx, 0), WW-1);
    int cy = min(max(yy, 0), HH-1);
    return cy*WW + cx;
}

__global__ __launch_bounds__(256) void k_main(const float* __restrict__ dep,
                                              const float* __restrict__ proj,
                                              const int*   __restrict__ rand_idx,
                                              const float* __restrict__ valid) {
    extern __shared__ float sm[];
    __half* s_depH  = reinterpret_cast<__half*>(sm);     // hi: 64*264 halves
    __half* s_depL  = s_depH + 64*ROWQ*8;                // lo: 64*264 halves
    __half* s_randH = s_depL + 64*ROWQ*8;                // 32*264 halves
    float*  s_sim   = reinterpret_cast<float*>(s_randH + 32*ROWQ*8); // 32*65
    float*  s_pos   = s_sim + NRAND*65;                  // 64
    float*  s_inv   = s_pos + 64;                        // 64
    float*  s_red   = s_inv + 64;                        // 4*65

    const int tid = threadIdx.x;
    const int tx  = tid & 31;
    const int ty  = tid >> 5;                  // warp id 0..7
    const int blocksPerBatch = NN/64;
    const int b  = blockIdx.x / blocksPerBatch;
    const int n0 = (blockIdx.x % blocksPerBatch) * 64;

    // ---- stage dep tile split fp16 hi/lo + partial norms (fp32) ----
    {
        const int px = tid & 63;               // pixel 0..63
        const int cg = tid >> 6;               // 0..3 -> chunks cg*8..cg*8+7
        const float* dsrc = dep + b*CC*NN + n0 + px;
        float ss = 0.0f;
        uint4* hrow = reinterpret_cast<uint4*>(s_depH) + px*ROWQ;
        uint4* lrow = reinterpret_cast<uint4*>(s_depL) + px*ROWQ;
        #pragma unroll
        for (int j = 0; j < 8; j++) {
            int chunk = cg*8 + j;
            float v[8];
            __half hi[8], lo[8];
            #pragma unroll
            for (int t = 0; t < 8; t++) {
                v[t] = dsrc[(chunk*8 + t)*NN];
                ss += v[t]*v[t];
                hi[t] = __float2half_rn(v[t]);
                lo[t] = __float2half_rn(v[t] - __half2float(hi[t]));
            }
            uint4 qh, ql;
            __half2 h;
            h = __halves2half2(hi[0], hi[1]); qh.x = *reinterpret_cast<unsigned*>(&h);
            h = __halves2half2(hi[2], hi[3]); qh.y = *reinterpret_cast<unsigned*>(&h);
            h = __halves2half2(hi[4], hi[5]); qh.z = *reinterpret_cast<unsigned*>(&h);
            h = __halves2half2(hi[6], hi[7]); qh.w = *reinterpret_cast<unsigned*>(&h);
            h = __halves2half2(lo[0], lo[1]); ql.x = *reinterpret_cast<unsigned*>(&h);
            h = __halves2half2(lo[2], lo[3]); ql.y = *reinterpret_cast<unsigned*>(&h);
            h = __halves2half2(lo[4], lo[5]); ql.z = *reinterpret_cast<unsigned*>(&h);
            h = __halves2half2(lo[6], lo[7]); ql.w = *reinterpret_cast<unsigned*>(&h);
            hrow[chunk] = qh;
            lrow[chunk] = ql;
        }
        s_red[cg*65 + px] = ss;
    }
    // ---- stage rand vectors (fp16 rows, padded) ----
    {
        int k = tid >> 3, part = tid & 7;
        int ridx = rand_idx[b*NRAND + k];
        const uint4* row = reinterpret_cast<const uint4*>(g_rgbTh + (size_t)(b*NN + ridx)*CC);
        uint4* drow = reinterpret_cast<uint4*>(s_randH) + k*ROWQ;
        #pragma unroll
        for (int i = 0; i < 4; i++) {
            int chunk = part + 8*i;
            drow[chunk] = row[chunk];
        }
    }
    __syncthreads();
    if (tid < 64) {
        float t = s_red[tid] + s_red[65 + tid] + s_red[2*65 + tid] + s_red[3*65 + tid];
        s_inv[tid] = 1.0f / fmaxf(sqrtf(t), 1e-12f);
    }
    __syncthreads();

    // ---- phase 3: rand GEMM on tensor cores, hi+lo split dep ----
    {
        unsigned aHBase = (unsigned)__cvta_generic_to_shared(s_depH);
        unsigned aLBase = (unsigned)__cvta_generic_to_shared(s_depL);
        unsigned bBase  = (unsigned)__cvta_generic_to_shared(s_randH);
        const int pxb = (ty & 3) * 16;
        const int kb0 = (ty >> 2) * 16;
        const unsigned aRow = (unsigned)(pxb + (tx & 15)) * ROWQ + (unsigned)(tx >> 4);
        const unsigned bRow0 = (unsigned)(kb0 + (tx & 7)) * ROWQ + (unsigned)((tx >> 3) & 1);
        const unsigned bRow1 = bRow0 + 8u*ROWQ;
        float d0[4] = {0,0,0,0}, d1[4] = {0,0,0,0};
        #pragma unroll
        for (int kk = 0; kk < 16; kk++) {
            unsigned ah[4], al[4], b0r[2], b1r[2];
            ldmx4(ah,  aHBase + (aRow  + 2*kk) * 16);
            ldmx4(al,  aLBase + (aRow  + 2*kk) * 16);
            ldmx2(b0r, bBase  + (bRow0 + 2*kk) * 16);
            ldmx2(b1r, bBase  + (bRow1 + 2*kk) * 16);
            mma16816(d0, ah, b0r);
            mma16816(d0, al, b0r);
            mma16816(d1, ah, b1r);
            mma16816(d1, al, b1r);
        }
        int pxl = pxb + (tx >> 2);
        int kl  = (tx & 3) * 2;
        s_sim[(kb0 + kl + 0)*65 + pxl]     = d0[0];
        s_sim[(kb0 + kl + 1)*65 + pxl]     = d0[1];
        s_sim[(kb0 + kl + 0)*65 + pxl + 8] = d0[2];
        s_sim[(kb0 + kl + 1)*65 + pxl + 8] = d0[3];
        s_sim[(kb0 + 8 + kl + 0)*65 + pxl]     = d1[0];
        s_sim[(kb0 + 8 + kl + 1)*65 + pxl]     = d1[1];
        s_sim[(kb0 + 8 + kl + 0)*65 + pxl + 8] = d1[2];
        s_sim[(kb0 + 8 + kl + 1)*65 + pxl + 8] = d1[3];
    }

    // ---- phase 2: pos_sim (warp handles 8 pixels), dep = hi + lo ----
    const float* projU = proj + b*2*NN;
    const float* projV = projU + NN;
    const uint4* depHQ = reinterpret_cast<const uint4*>(s_depH);
    const uint4* depLQ = reinterpret_cast<const uint4*>(s_depL);
    #pragma unroll
    for (int q = 0; q < 8; q++) {
        int px = ty*8 + q;
        int n  = n0 + px;
        float pu = projU[n], pv = projV[n];
        float x0f = floorf(pu), y0f = floorf(pv);
        float wx = pu - x0f, wy = pv - y0f;
        int x0 = (int)x0f, y0 = (int)y0f;
        float w00 = (1.0f-wx)*(1.0f-wy), w10 = wx*(1.0f-wy);
        float w01 = (1.0f-wx)*wy,        w11 = wx*wy;
        int i00 = corner_idx(x0,   y0,   w00);
        int i10 = corner_idx(x0+1, y0,   w10);
        int i01 = corner_idx(x0,   y0+1, w01);
        int i11 = corner_idx(x0+1, y0+1, w11);
        const uint4* r00 = reinterpret_cast<const uint4*>(g_rgbTh + (size_t)(b*NN + i00)*CC);
        const uint4* r10 = reinterpret_cast<const uint4*>(g_rgbTh + (size_t)(b*NN + i10)*CC);
        const uint4* r01 = reinterpret_cast<const uint4*>(g_rgbTh + (size_t)(b*NN + i01)*CC);
        const uint4* r11 = reinterpret_cast<const uint4*>(g_rgbTh + (size_t)(b*NN + i11)*CC);
        uint4 dqh = depHQ[px*ROWQ + tx];
        uint4 dql = depLQ[px*ROWQ + tx];
        uint4 q00 = r00[tx], q10 = r10[tx], q01 = r01[tx], q11 = r11[tx];
        float pacc = 0.0f;
        const unsigned* duh = &dqh.x;
        const unsigned* dul = &dql.x;
        const unsigned* u00 = &q00.x;
        const unsigned* u10 = &q10.x;
        const unsigned* u01 = &q01.x;
        const unsigned* u11 = &q11.x;
        #pragma unroll
        for (int j = 0; j < 4; j++) {
            float2 dh = __half22float2(*reinterpret_cast<const __half2*>(&duh[j]));
            float2 dl = __half22float2(*reinterpret_cast<const __half2*>(&dul[j]));
            float dx = dh.x + dl.x, dy = dh.y + dl.y;
            float2 a00 = __half22float2(*reinterpret_cast<const __half2*>(&u00[j]));
            float2 a10 = __half22float2(*reinterpret_cast<const __half2*>(&u10[j]));
            float2 a01 = __half22float2(*reinterpret_cast<const __half2*>(&u01[j]));
            float2 a11 = __half22float2(*reinterpret_cast<const __half2*>(&u11[j]));
            pacc += dx*(w00*a00.x + w10*a10.x + w01*a01.x + w11*a11.x);
            pacc += dy*(w00*a00.y + w10*a10.y + w01*a01.y + w11*a11.y);
        }
        #pragma unroll
        for (int o = 16; o; o >>= 1) pacc += __shfl_xor_sync(0xffffffffu, pacc, o);
        if (tx == 0) s_pos[px] = pacc;
    }

    // ---- grid-point dep dump (hi+lo -> fp32, normalized * TEMP_INV) ----
    const int v_row = n0 >> 7;
    const int u0 = n0 & 127;
    const bool gridRow = ((v_row & 7) == 0);
    if (gridRow) {
        int px = ty*8;   // u%8==0 positions within the 64-px tile
        int p = ((v_row >> 3) << 4) + ((u0 + px) >> 3);
        float sc = s_inv[px] * TEMP_INV;
        float* dst = g_depGrid + (b*NPOS + p)*CC;
        uint4 dqh = depHQ[px*ROWQ + tx];
        uint4 dql = depLQ[px*ROWQ + tx];
        const unsigned* duh = &dqh.x;
        const unsigned* dul = &dql.x;
        float4 o0, o1;
        float2 fh, fl;
        fh = __half22float2(*reinterpret_cast<const __half2*>(&duh[0]));
        fl = __half22float2(*reinterpret_cast<const __half2*>(&dul[0]));
        o0.x = (fh.x+fl.x)*sc; o0.y = (fh.y+fl.y)*sc;
        fh = __half22float2(*reinterpret_cast<const __half2*>(&duh[1]));
        fl = __half22float2(*reinterpret_cast<const __half2*>(&dul[1]));
        o0.z = (fh.x+fl.x)*sc; o0.w = (fh.y+fl.y)*sc;
        fh = __half22float2(*reinterpret_cast<const __half2*>(&duh[2]));
        fl = __half22float2(*reinterpret_cast<const __half2*>(&dul[2]));
        o1.x = (fh.x+fl.x)*sc; o1.y = (fh.y+fl.y)*sc;
        fh = __half22float2(*reinterpret_cast<const __half2*>(&duh[3]));
        fl = __half22float2(*reinterpret_cast<const __half2*>(&dul[3]));
        o1.z = (fh.x+fl.x)*sc; o1.w = (fh.y+fl.y)*sc;
        reinterpret_cast<float4*>(dst + tx*8)[0] = o0;
        reinterpret_cast<float4*>(dst + tx*8)[1] = o1;
    }
    __syncthreads();

    // ---- phase 4: logsumexp / max + fused loss for non-grid pixels ----
    float wl = 0.0f, wm = 0.0f, wc = 0.0f;
    #pragma unroll
    for (int q = 0; q < 8; q++) {
        int px = ty*8 + q;
        float scale = s_inv[px] * TEMP_INV;
        float pos = s_pos[px] * scale;
        float v = s_sim[tx*65 + px] * scale;
        float mneg = v;
        #pragma unroll
        for (int o = 16; o; o >>= 1) mneg = fmaxf(mneg, __shfl_xor_sync(0xffffffffu, mneg, o));
        float m = fmaxf(pos, mneg);
        float e = expf(v - m);
        #pragma unroll
        for (int o = 16; o; o >>= 1) e += __shfl_xor_sync(0xffffffffu, e, o);
        if (tx == 0) {
            float lse = m + logf(e + expf(pos - m));
            bool isGrid = gridRow && (q == 0);   // px%8==0 <=> q==0
            if (isGrid) {
                int p = ((v_row >> 3) << 4) + ((u0 + px) >> 3);
                g_posG[b*NPOS + p] = pos;
                g_lseG[b*NPOS + p] = lse;
                g_mxG [b*NPOS + p] = mneg;
            } else {
                float mask = valid[b*NN + n0 + px];
                wl += (lse - pos) * mask;
                wm += mask;
                wc += (pos > mneg && mask > 0.5f) ? 1.0f : 0.0f;
            }
        }
    }
    __syncthreads();
    if (tx == 0) {
        s_red[ty] = wl;
        s_red[8 + ty] = wm;
        s_red[16 + ty] = wc;
    }
    __syncthreads();
    if (tid == 0) {
        float a = 0.f, b2 = 0.f, c2 = 0.f;
        #pragma unroll
        for (int j = 0; j < 8; j++) { a += s_red[j]; b2 += s_red[8+j]; c2 += s_red[16+j]; }
        atomicAdd(&g_acc[0], a);
        atomicAdd(&g_acc[1], b2);
        atomicAdd(&g_acc[2], c2);
    }
}

// ---------------- kernel 3: hard negatives + grid-pixel loss + epilogue ------
__global__ __launch_bounds__(256) void k_hard(const float* __restrict__ proj,
                                              const int*   __restrict__ offu,
                                              const int*   __restrict__ offv,
                                              const float* __restrict__ valid,
                                              float* __restrict__ out) {
    __shared__ float s_depv[CC];
    __shared__ float s_hsim[NHARD];
    const int tid = threadIdx.x;
    const int tx = tid & 31;
    const int ty = tid >> 5;
    const int b = blockIdx.x >> 8;
    const int p = blockIdx.x & 255;
    const int gh = (p >> 4) * 8;
    const int gw = (p & 15) * 8;
    const int ng = gh*WW + gw;

    s_depv[tid] = g_depGrid[(b*NPOS + p)*CC + tid];
    __syncthreads();

    float pu = proj[b*2*NN + ng];
    float pv = proj[b*2*NN + NN + ng];
    int posu = (int)fminf(fmaxf(pu, 0.0f), (float)(WW-1));
    int posv = (int)fminf(fmaxf(pv, 0.0f), (float)(HH-1));

    // precompute all 12 row pointers, then issue all 12 gathers concurrently
    const uint4* r[12];
    #pragma unroll
    for (int j = 0; j < 12; j++) {
        int h = ty*12 + j;
        int ou = offu[(b*NHARD + h)*NPOS + p];
        int ov = offv[(b*NHARD + h)*NPOS + p];
        if (ou == 0 && ov == 0) ou = 1;
        int hu = min(max(posu + ou, 0), WW-1);
        int hv = min(max(posv + ov, 0), HH-1);
        r[j] = reinterpret_cast<const uint4*>(g_rgbTh + (size_t)(b*NN + hv*WW + hu)*CC);
    }
    uint4 q[12];
    #pragma unroll
    for (int j = 0; j < 12; j++) q[j] = r[j][tx];

    const float4* dv = reinterpret_cast<const float4*>(s_depv);
    float4 d0 = dv[2*tx];
    float4 d1 = dv[2*tx + 1];
    float acc[12];
    #pragma unroll
    for (int j = 0; j < 12; j++) {
        float2 f0 = __half22float2(*reinterpret_cast<__half2*>(&q[j].x));
        float2 f1 = __half22float2(*reinterpret_cast<__half2*>(&q[j].y));
        float2 f2 = __half22float2(*reinterpret_cast<__half2*>(&q[j].z));
        float2 f3 = __half22float2(*reinterpret_cast<__half2*>(&q[j].w));
        float a = 0.0f;
        a += d0.x*f0.x; a += d0.y*f0.y; a += d0.z*f1.x; a += d0.w*f1.y;
        a += d1.x*f2.x; a += d1.y*f2.y; a += d1.z*f3.x; a += d1.w*f3.y;
        acc[j] = a;
    }
    #pragma unroll
    for (int o = 16; o; o >>= 1) {
        #pragma unroll
        for (int j = 0; j < 12; j++)
            acc[j] += __shfl_xor_sync(0xffffffffu, acc[j], o);
    }
    if (tx == 0) {
        #pragma unroll
        for (int j = 0; j < 12; j++) s_hsim[ty*12 + j] = acc[j];
    }
    __syncthreads();

    if (tid < 32) {
        float v0 = s_hsim[tx];
        float v1 = s_hsim[tx + 32];
        float v2 = s_hsim[tx + 64];
        float m = fmaxf(fmaxf(v0, v1), v2);
        #pragma unroll
        for (int o = 16; o; o >>= 1) m = fmaxf(m, __shfl_xor_sync(0xffffffffu, m, o));
        float se = expf(v0 - m) + expf(v1 - m) + expf(v2 - m);
        #pragma unroll
        for (int o = 16; o; o >>= 1) se += __shfl_xor_sync(0xffffffffu, se, o);
        if (tx == 0) {
            float lse_h = m + logf(se);
            int bp = b*NPOS + p;
            float pos = g_posG[bp];
            float lse0 = g_lseG[bp];
            float mx0 = g_mxG[bp];
            float mm = fmaxf(lse0, lse_h);
            float lse = mm + logf(expf(lse0 - mm) + expf(lse_h - mm));
            float mx = fmaxf(mx0, m);
            float mask = valid[b*NN + ng];
            float lossp = (lse - pos) * mask;
            float corr = (pos > mx && mask > 0.5f) ? 1.0f : 0.0f;
            atomicAdd(&g_acc[0], lossp);
            atomicAdd(&g_acc[1], mask);
            atomicAdd(&g_acc[2], corr);
            __threadfence();
            unsigned t = atomicAdd(&g_done, 1u);
            if (t == (unsigned)(BB*NPOS) - 1u) {
                __threadfence();
                float denom = fmaxf(g_acc[1], 1.0f);
                out[0] = g_acc[0] / denom;
                out[1] = g_acc[2] / denom * 100.0f;
            }
        }
    }
}

// ---------------- launch -------------------------------------------------------
extern "C" void kernel_launch(void* const* d_in, const int* in_sizes, int n_in,
                              void* d_out, int out_size) {
    const float* rgb   = (const float*)d_in[0];
    const float* dep   = (const float*)d_in[1];
    const float* proj  = (const float*)d_in[2];
    const float* valid = (const float*)d_in[3];
    const int*   ridx  = (const int*)d_in[4];
    const int*   offu  = (const int*)d_in[5];
    const int*   offv  = (const int*)d_in[6];
    float* out = (float*)d_out;

    const int smem_main = 64*ROWQ*16*2 + 32*ROWQ*16
                        + (NRAND*65 + 64 + 64 + 4*65) * (int)sizeof(float);
    cudaFuncSetAttribute(k_main, cudaFuncAttributeMaxDynamicSharedMemorySize, smem_main);

    k_norm_t<<<BB*NN/32, 256>>>(rgb);
    k_main<<<BB*NN/64, 256, smem_main>>>(dep, proj, ridx, valid);
    k_hard<<<BB*NPOS, 256>>>(proj, offu, offv, valid, out);
}

// round 10
// speedup vs baseline: 2.3846x; 1.1177x over previous
#include <cuda_runtime.h>
#include <cuda_fp16.h>
#include <math.h>

#define BB 8
#define CC 256
#define HH 128
#define WW 128
#define NN (HH*WW)          // 16384
#define NPOS 256
#define NHARD 96
#define NRAND 32
#define TEMP_INV (1.0f/0.07f)

#define ROWQ 33             // quads (16B units) per padded fp16 row (264 halves)

// ---------------- scratch (static device globals; no allocation) ------------
__device__ __half g_rgbTh[BB*NN*CC];    // normalized rgb (fp16), [b][px][ch]
__device__ float g_depGrid[BB*NPOS*CC]; // normalized*TEMP_INV dep at grid pts
__device__ float g_posG[BB*NPOS];       // pos_sim at grid points
__device__ float g_lseG[BB*NPOS];       // base lse at grid points
__device__ float g_mxG[BB*NPOS];        // rand max at grid points
__device__ float g_acc[3];              // loss_sum, mask_sum, correct_sum
__device__ unsigned g_done;

// ---------------- mma/ldmatrix helpers ---------------------------------------
__device__ __forceinline__ void ldmx4(unsigned* r, unsigned addr) {
    asm volatile("ldmatrix.sync.aligned.m8n8.x4.shared.b16 {%0,%1,%2,%3}, [%4];"
                 : "=r"(r[0]), "=r"(r[1]), "=r"(r[2]), "=r"(r[3]) : "r"(addr));
}
__device__ __forceinline__ void ldmx2(unsigned* r, unsigned addr) {
    asm volatile("ldmatrix.sync.aligned.m8n8.x2.shared.b16 {%0,%1}, [%2];"
                 : "=r"(r[0]), "=r"(r[1]) : "r"(addr));
}
__device__ __forceinline__ void mma16816(float* d, const unsigned* a, const unsigned* b) {
    asm volatile(
        "mma.sync.aligned.m16n8k16.row.col.f32.f16.f16.f32 "
        "{%0,%1,%2,%3}, {%4,%5,%6,%7}, {%8,%9}, {%0,%1,%2,%3};"
        : "+f"(d[0]), "+f"(d[1]), "+f"(d[2]), "+f"(d[3])
        : "r"(a[0]), "r"(a[1]), "r"(a[2]), "r"(a[3]),
          "r"(b[0]), "r"(b[1]));
}

// ---------------- kernel 1: normalize + transpose (conflict-free) ------------
__global__ __launch_bounds__(256) void k_norm_t(const float* __restrict__ in) {
    __shared__ float s_tile[CC*33];
    __shared__ float s_red[8*33];
    __shared__ float s_inv[32];
    __shared__ __half s_half[32*ROWQ*8];   // 32 px * 264 halves (16.9 KB)
    const int tid = threadIdx.x;
    const int tx = tid & 31;        // pixel in tile
    const int ty = tid >> 5;        // warp id / channel subset
    const int blocksPerBatch = NN/32;
    const int b  = blockIdx.x / blocksPerBatch;
    const int n0 = (blockIdx.x % blocksPerBatch) * 32;

    if (blockIdx.x == 0 && tid < 3) g_acc[tid] = 0.0f;
    if (blockIdx.x == 0 && tid == 3) g_done = 0;

    // ---- phase A: load tile + fused sum-of-squares (channels == ty mod 8) ----
    const float* src = in + b*CC*NN + n0;
    float ss = 0.0f;
    #pragma unroll 8
    for (int i = 0; i < 32; i++) {
        int c = i*8 + ty;
        float v = src[c*NN + tx];
        s_tile[c*33 + tx] = v;
        ss += v*v;
    }
    s_red[ty*33 + tx] = ss;
    __syncthreads();
    if (ty == 0) {
        float t = 0.0f;
        #pragma unroll
        for (int j = 0; j < 8; j++) t += s_red[j*33 + tx];
        s_inv[tx] = 1.0f / fmaxf(sqrtf(t), 1e-12f);
    }
    __syncthreads();

    // ---- phase B: scale + fp16 pack, lane = pixel (conflict-free LDS/STS) ----
    {
        const int px = tx;
        float inv = s_inv[px];
        uint4* hrow = reinterpret_cast<uint4*>(s_half) + px*ROWQ;
        #pragma unroll
        for (int cc2 = 0; cc2 < 4; cc2++) {
            int ch = ty*4 + cc2;               // chunk: channels ch*8..ch*8+7
            float v[8];
            #pragma unroll
            for (int j = 0; j < 8; j++) v[j] = s_tile[(ch*8 + j)*33 + px] * inv;
            uint4 q;
            __half2 h;
            h = __floats2half2_rn(v[0], v[1]); q.x = *reinterpret_cast<unsigned*>(&h);
            h = __floats2half2_rn(v[2], v[3]); q.y = *reinterpret_cast<unsigned*>(&h);
            h = __floats2half2_rn(v[4], v[5]); q.z = *reinterpret_cast<unsigned*>(&h);
            h = __floats2half2_rn(v[6], v[7]); q.w = *reinterpret_cast<unsigned*>(&h);
            hrow[ch] = q;
        }
    }
    __syncthreads();

    // ---- phase C: coalesced uint4 copy smem -> global ----
    {
        uint4* dst = reinterpret_cast<uint4*>(g_rgbTh + (size_t)(b*NN + n0)*CC);
        const uint4* srcq = reinterpret_cast<const uint4*>(s_half);
        const int cb = tid & 31;               // chunk
        const int pq = tid >> 5;               // pixel sub-index
        #pragma unroll
        for (int it = 0; it < 4; it++) {
            int px = it*8 + pq;
            dst[px*(CC/8) + cb] = srcq[px*ROWQ + cb];
        }
    }
}

// ---------------- kernel 2: main pass + fused loss (non-grid pixels) ---------
__device__ __forceinline__ int corner_idx(int xx, int yy, float& w) {
    bool v = (xx >= 0) & (xx < WW) & (yy >= 0) & (yy < HH);
    if (!v) w = 0.0f;
    int cx = min(max(xx, 0), WW-1);
    int cy = min(max(yy, 0), HH-1);
    return cy*WW + cx;
}

__global__ __launch_bounds__(256) void k_main(const float* __restrict__ dep,
                                              const float* __restrict__ proj,
                                              const int*   __restrict__ rand_idx,
                                              const float* __restrict__ valid) {
    extern __shared__ float sm[];
    __half* s_depH  = reinterpret_cast<__half*>(sm);     // hi: 64*264 halves
    __half* s_depL  = s_depH + 64*ROWQ*8;                // lo: 64*264 halves
    __half* s_randH = s_depL + 64*ROWQ*8;                // 32*264 halves
    float*  s_sim   = reinterpret_cast<float*>(s_randH + 32*ROWQ*8); // 32*65
    float*  s_pos   = s_sim + NRAND*65;                  // 64
    float*  s_inv   = s_pos + 64;                        // 64
    float*  s_red   = s_inv + 64;                        // 4*65

    const int tid = threadIdx.x;
    const int tx  = tid & 31;
    const int ty  = tid >> 5;                  // warp id 0..7
    const int blocksPerBatch = NN/64;
    const int b  = blockIdx.x / blocksPerBatch;
    const int n0 = (blockIdx.x % blocksPerBatch) * 64;

    // ---- stage dep tile split fp16 hi/lo + partial norms (fp32) ----
    {
        const int px = tid & 63;               // pixel 0..63
        const int cg = tid >> 6;               // 0..3 -> chunks cg*8..cg*8+7
        const float* dsrc = dep + b*CC*NN + n0 + px;
        float ss = 0.0f;
        uint4* hrow = reinterpret_cast<uint4*>(s_depH) + px*ROWQ;
        uint4* lrow = reinterpret_cast<uint4*>(s_depL) + px*ROWQ;
        #pragma unroll
        for (int j = 0; j < 8; j++) {
            int chunk = cg*8 + j;
            float v[8];
            __half hi[8], lo[8];
            #pragma unroll
            for (int t = 0; t < 8; t++) {
                v[t] = dsrc[(chunk*8 + t)*NN];
                ss += v[t]*v[t];
                hi[t] = __float2half_rn(v[t]);
                lo[t] = __float2half_rn(v[t] - __half2float(hi[t]));
            }
            uint4 qh, ql;
            __half2 h;
            h = __halves2half2(hi[0], hi[1]); qh.x = *reinterpret_cast<unsigned*>(&h);
            h = __halves2half2(hi[2], hi[3]); qh.y = *reinterpret_cast<unsigned*>(&h);
            h = __halves2half2(hi[4], hi[5]); qh.z = *reinterpret_cast<unsigned*>(&h);
            h = __halves2half2(hi[6], hi[7]); qh.w = *reinterpret_cast<unsigned*>(&h);
            h = __halves2half2(lo[0], lo[1]); ql.x = *reinterpret_cast<unsigned*>(&h);
            h = __halves2half2(lo[2], lo[3]); ql.y = *reinterpret_cast<unsigned*>(&h);
            h = __halves2half2(lo[4], lo[5]); ql.z = *reinterpret_cast<unsigned*>(&h);
            h = __halves2half2(lo[6], lo[7]); ql.w = *reinterpret_cast<unsigned*>(&h);
            hrow[chunk] = qh;
            lrow[chunk] = ql;
        }
        s_red[cg*65 + px] = ss;
    }
    // ---- stage rand vectors (fp16 rows, padded) ----
    {
        int k = tid >> 3, part = tid & 7;
        int ridx = rand_idx[b*NRAND + k];
        const uint4* row = reinterpret_cast<const uint4*>(g_rgbTh + (size_t)(b*NN + ridx)*CC);
        uint4* drow = reinterpret_cast<uint4*>(s_randH) + k*ROWQ;
        #pragma unroll
        for (int i = 0; i < 4; i++) {
            int chunk = part + 8*i;
            drow[chunk] = row[chunk];
        }
    }
    __syncthreads();
    if (tid < 64) {
        float t = s_red[tid] + s_red[65 + tid] + s_red[2*65 + tid] + s_red[3*65 + tid];
        s_inv[tid] = 1.0f / fmaxf(sqrtf(t), 1e-12f);
    }
    __syncthreads();

    // ---- phase 3: rand GEMM on tensor cores, hi+lo split dep ----
    {
        unsigned aHBase = (unsigned)__cvta_generic_to_shared(s_depH);
        unsigned aLBase = (unsigned)__cvta_generic_to_shared(s_depL);
        unsigned bBase  = (unsigned)__cvta_generic_to_shared(s_randH);
        const int pxb = (ty & 3) * 16;
        const int kb0 = (ty >> 2) * 16;
        const unsigned aRow = (unsigned)(pxb + (tx & 15)) * ROWQ + (unsigned)(tx >> 4);
        const unsigned bRow0 = (unsigned)(kb0 + (tx & 7)) * ROWQ + (unsigned)((tx >> 3) & 1);
        const unsigned bRow1 = bRow0 + 8u*ROWQ;
        float d0[4] = {0,0,0,0}, d1[4] = {0,0,0,0};
        #pragma unroll
        for (int kk = 0; kk < 16; kk++) {
            unsigned ah[4], al[4], b0r[2], b1r[2];
            ldmx4(ah,  aHBase + (aRow  + 2*kk) * 16);
            ldmx4(al,  aLBase + (aRow  + 2*kk) * 16);
            ldmx2(b0r, bBase  + (bRow0 + 2*kk) * 16);
            ldmx2(b1r, bBase  + (bRow1 + 2*kk) * 16);
            mma16816(d0, ah, b0r);
            mma16816(d0, al, b0r);
            mma16816(d1, ah, b1r);
            mma16816(d1, al, b1r);
        }
        int pxl = pxb + (tx >> 2);
        int kl  = (tx & 3) * 2;
        s_sim[(kb0 + kl + 0)*65 + pxl]     = d0[0];
        s_sim[(kb0 + kl + 1)*65 + pxl]     = d0[1];
        s_sim[(kb0 + kl + 0)*65 + pxl + 8] = d0[2];
        s_sim[(kb0 + kl + 1)*65 + pxl + 8] = d0[3];
        s_sim[(kb0 + 8 + kl + 0)*65 + pxl]     = d1[0];
        s_sim[(kb0 + 8 + kl + 1)*65 + pxl]     = d1[1];
        s_sim[(kb0 + 8 + kl + 0)*65 + pxl + 8] = d1[2];
        s_sim[(kb0 + 8 + kl + 1)*65 + pxl + 8] = d1[3];
    }

    // ---- phase 2: pos_sim (warp handles 8 pixels), dep = hi + lo ----
    const float* projU = proj + b*2*NN;
    const float* projV = projU + NN;
    const uint4* depHQ = reinterpret_cast<const uint4*>(s_depH);
    const uint4* depLQ = reinterpret_cast<const uint4*>(s_depL);
    #pragma unroll
    for (int q = 0; q < 8; q++) {
        int px = ty*8 + q;
        int n  = n0 + px;
        float pu = projU[n], pv = projV[n];
        float x0f = floorf(pu), y0f = floorf(pv);
        float wx = pu - x0f, wy = pv - y0f;
        int x0 = (int)x0f, y0 = (int)y0f;
        float w00 = (1.0f-wx)*(1.0f-wy), w10 = wx*(1.0f-wy);
        float w01 = (1.0f-wx)*wy,        w11 = wx*wy;
        int i00 = corner_idx(x0,   y0,   w00);
        int i10 = corner_idx(x0+1, y0,   w10);
        int i01 = corner_idx(x0,   y0+1, w01);
        int i11 = corner_idx(x0+1, y0+1, w11);
        const uint4* r00 = reinterpret_cast<const uint4*>(g_rgbTh + (size_t)(b*NN + i00)*CC);
        const uint4* r10 = reinterpret_cast<const uint4*>(g_rgbTh + (size_t)(b*NN + i10)*CC);
        const uint4* r01 = reinterpret_cast<const uint4*>(g_rgbTh + (size_t)(b*NN + i01)*CC);
        const uint4* r11 = reinterpret_cast<const uint4*>(g_rgbTh + (size_t)(b*NN + i11)*CC);
        uint4 dqh = depHQ[px*ROWQ + tx];
        uint4 dql = depLQ[px*ROWQ + tx];
        uint4 q00 = r00[tx], q10 = r10[tx], q01 = r01[tx], q11 = r11[tx];
        float pacc = 0.0f;
        const unsigned* duh = &dqh.x;
        const unsigned* dul = &dql.x;
        const unsigned* u00 = &q00.x;
        const unsigned* u10 = &q10.x;
        const unsigned* u01 = &q01.x;
        const unsigned* u11 = &q11.x;
        #pragma unroll
        for (int j = 0; j < 4; j++) {
            float2 dh = __half22float2(*reinterpret_cast<const __half2*>(&duh[j]));
            float2 dl = __half22float2(*reinterpret_cast<const __half2*>(&dul[j]));
            float dx = dh.x + dl.x, dy = dh.y + dl.y;
            float2 a00 = __half22float2(*reinterpret_cast<const __half2*>(&u00[j]));
            float2 a10 = __half22float2(*reinterpret_cast<const __half2*>(&u10[j]));
            float2 a01 = __half22float2(*reinterpret_cast<const __half2*>(&u01[j]));
            float2 a11 = __half22float2(*reinterpret_cast<const __half2*>(&u11[j]));
            pacc += dx*(w00*a00.x + w10*a10.x + w01*a01.x + w11*a11.x);
            pacc += dy*(w00*a00.y + w10*a10.y + w01*a01.y + w11*a11.y);
        }
        #pragma unroll
        for (int o = 16; o; o >>= 1) pacc += __shfl_xor_sync(0xffffffffu, pacc, o);
        if (tx == 0) s_pos[px] = pacc;
    }

    // ---- grid-point dep dump (hi+lo -> fp32, normalized * TEMP_INV) ----
    const int v_row = n0 >> 7;
    const int u0 = n0 & 127;
    const bool gridRow = ((v_row & 7) == 0);
    if (gridRow) {
        int px = ty*8;   // u%8==0 positions within the 64-px tile
        int p = ((v_row >> 3) << 4) + ((u0 + px) >> 3);
        float sc = s_inv[px] * TEMP_INV;
        float* dst = g_depGrid + (b*NPOS + p)*CC;
        uint4 dqh = depHQ[px*ROWQ + tx];
        uint4 dql = depLQ[px*ROWQ + tx];
        const unsigned* duh = &dqh.x;
        const unsigned* dul = &dql.x;
        float4 o0, o1;
        float2 fh, fl;
        fh = __half22float2(*reinterpret_cast<const __half2*>(&duh[0]));
        fl = __half22float2(*reinterpret_cast<const __half2*>(&dul[0]));
        o0.x = (fh.x+fl.x)*sc; o0.y = (fh.y+fl.y)*sc;
        fh = __half22float2(*reinterpret_cast<const __half2*>(&duh[1]));
        fl = __half22float2(*reinterpret_cast<const __half2*>(&dul[1]));
        o0.z = (fh.x+fl.x)*sc; o0.w = (fh.y+fl.y)*sc;
        fh = __half22float2(*reinterpret_cast<const __half2*>(&duh[2]));
        fl = __half22float2(*reinterpret_cast<const __half2*>(&dul[2]));
        o1.x = (fh.x+fl.x)*sc; o1.y = (fh.y+fl.y)*sc;
        fh = __half22float2(*reinterpret_cast<const __half2*>(&duh[3]));
        fl = __half22float2(*reinterpret_cast<const __half2*>(&dul[3]));
        o1.z = (fh.x+fl.x)*sc; o1.w = (fh.y+fl.y)*sc;
        reinterpret_cast<float4*>(dst + tx*8)[0] = o0;
        reinterpret_cast<float4*>(dst + tx*8)[1] = o1;
    }
    __syncthreads();

    // ---- phase 4: logsumexp / max + fused loss for non-grid pixels ----
    float wl = 0.0f, wm = 0.0f, wc = 0.0f;
    #pragma unroll
    for (int q = 0; q < 8; q++) {
        int px = ty*8 + q;
        float scale = s_inv[px] * TEMP_INV;
        float pos = s_pos[px] * scale;
        float v = s_sim[tx*65 + px] * scale;
        float mneg = v;
        #pragma unroll
        for (int o = 16; o; o >>= 1) mneg = fmaxf(mneg, __shfl_xor_sync(0xffffffffu, mneg, o));
        float m = fmaxf(pos, mneg);
        float e = expf(v - m);
        #pragma unroll
        for (int o = 16; o; o >>= 1) e += __shfl_xor_sync(0xffffffffu, e, o);
        if (tx == 0) {
            float lse = m + logf(e + expf(pos - m));
            bool isGrid = gridRow && (q == 0);   // px%8==0 <=> q==0
            if (isGrid) {
                int p = ((v_row >> 3) << 4) + ((u0 + px) >> 3);
                g_posG[b*NPOS + p] = pos;
                g_lseG[b*NPOS + p] = lse;
                g_mxG [b*NPOS + p] = mneg;
            } else {
                float mask = valid[b*NN + n0 + px];
                wl += (lse - pos) * mask;
                wm += mask;
                wc += (pos > mneg && mask > 0.5f) ? 1.0f : 0.0f;
            }
        }
    }
    __syncthreads();
    if (tx == 0) {
        s_red[ty] = wl;
        s_red[8 + ty] = wm;
        s_red[16 + ty] = wc;
    }
    __syncthreads();
    if (tid == 0) {
        float a = 0.f, b2 = 0.f, c2 = 0.f;
        #pragma unroll
        for (int j = 0; j < 8; j++) { a += s_red[j]; b2 += s_red[8+j]; c2 += s_red[16+j]; }
        atomicAdd(&g_acc[0], a);
        atomicAdd(&g_acc[1], b2);
        atomicAdd(&g_acc[2], c2);
    }
}

// ---------------- kernel 3: hard negatives + grid-pixel loss + epilogue ------
__global__ __launch_bounds__(256) void k_hard(const float* __restrict__ proj,
                                              const int*   __restrict__ offu,
                                              const int*   __restrict__ offv,
                                              const float* __restrict__ valid,
                                              float* __restrict__ out) {
    __shared__ float s_depv[CC];
    __shared__ float s_hsim[NHARD];
    const int tid = threadIdx.x;
    const int tx = tid & 31;
    const int ty = tid >> 5;
    const int b = blockIdx.x >> 8;
    const int p = blockIdx.x & 255;
    const int gh = (p >> 4) * 8;
    const int gw = (p & 15) * 8;
    const int ng = gh*WW + gw;

    s_depv[tid] = g_depGrid[(b*NPOS + p)*CC + tid];
    __syncthreads();

    float pu = proj[b*2*NN + ng];
    float pv = proj[b*2*NN + NN + ng];
    int posu = (int)fminf(fmaxf(pu, 0.0f), (float)(WW-1));
    int posv = (int)fminf(fmaxf(pv, 0.0f), (float)(HH-1));

    // precompute all 12 row pointers, then issue all 12 gathers concurrently
    const uint4* r[12];
    #pragma unroll
    for (int j = 0; j < 12; j++) {
        int h = ty*12 + j;
        int ou = offu[(b*NHARD + h)*NPOS + p];
        int ov = offv[(b*NHARD + h)*NPOS + p];
        if (ou == 0 && ov == 0) ou = 1;
        int hu = min(max(posu + ou, 0), WW-1);
        int hv = min(max(posv + ov, 0), HH-1);
        r[j] = reinterpret_cast<const uint4*>(g_rgbTh + (size_t)(b*NN + hv*WW + hu)*CC);
    }
    uint4 q[12];
    #pragma unroll
    for (int j = 0; j < 12; j++) q[j] = r[j][tx];

    const float4* dv = reinterpret_cast<const float4*>(s_depv);
    float4 d0 = dv[2*tx];
    float4 d1 = dv[2*tx + 1];
    float acc[12];
    #pragma unroll
    for (int j = 0; j < 12; j++) {
        float2 f0 = __half22float2(*reinterpret_cast<__half2*>(&q[j].x));
        float2 f1 = __half22float2(*reinterpret_cast<__half2*>(&q[j].y));
        float2 f2 = __half22float2(*reinterpret_cast<__half2*>(&q[j].z));
        float2 f3 = __half22float2(*reinterpret_cast<__half2*>(&q[j].w));
        float a = 0.0f;
        a += d0.x*f0.x; a += d0.y*f0.y; a += d0.z*f1.x; a += d0.w*f1.y;
        a += d1.x*f2.x; a += d1.y*f2.y; a += d1.z*f3.x; a += d1.w*f3.y;
        acc[j] = a;
    }
    #pragma unroll
    for (int o = 16; o; o >>= 1) {
        #pragma unroll
        for (int j = 0; j < 12; j++)
            acc[j] += __shfl_xor_sync(0xffffffffu, acc[j], o);
    }
    if (tx == 0) {
        #pragma unroll
        for (int j = 0; j < 12; j++) s_hsim[ty*12 + j] = acc[j];
    }
    __syncthreads();

    if (tid < 32) {
        float v0 = s_hsim[tx];
        float v1 = s_hsim[tx + 32];
        float v2 = s_hsim[tx + 64];
        float m = fmaxf(fmaxf(v0, v1), v2);
        #pragma unroll
        for (int o = 16; o; o >>= 1) m = fmaxf(m, __shfl_xor_sync(0xffffffffu, m, o));
        float se = expf(v0 - m) + expf(v1 - m) + expf(v2 - m);
        #pragma unroll
        for (int o = 16; o; o >>= 1) se += __shfl_xor_sync(0xffffffffu, se, o);
        if (tx == 0) {
            float lse_h = m + logf(se);
            int bp = b*NPOS + p;
            float pos = g_posG[bp];
            float lse0 = g_lseG[bp];
            float mx0 = g_mxG[bp];
            float mm = fmaxf(lse0, lse_h);
            float lse = mm + logf(expf(lse0 - mm) + expf(lse_h - mm));
            float mx = fmaxf(mx0, m);
            float mask = valid[b*NN + ng];
            float lossp = (lse - pos) * mask;
            float corr = (pos > mx && mask > 0.5f) ? 1.0f : 0.0f;
            atomicAdd(&g_acc[0], lossp);
            atomicAdd(&g_acc[1], mask);
            atomicAdd(&g_acc[2], corr);
            __threadfence();
            unsigned t = atomicAdd(&g_done, 1u);
            if (t == (unsigned)(BB*NPOS) - 1u) {
                __threadfence();
                float denom = fmaxf(g_acc[1], 1.0f);
                out[0] = g_acc[0] / denom;
                out[1] = g_acc[2] / denom * 100.0f;
            }
        }
    }
}

// ---------------- launch -------------------------------------------------------
extern "C" void kernel_launch(void* const* d_in, const int* in_sizes, int n_in,
                              void* d_out, int out_size) {
    const float* rgb   = (const float*)d_in[0];
    const float* dep   = (const float*)d_in[1];
    const float* proj  = (const float*)d_in[2];
    const float* valid = (const float*)d_in[3];
    const int*   ridx  = (const int*)d_in[4];
    const int*   offu  = (const int*)d_in[5];
    const int*   offv  = (const int*)d_in[6];
    float* out = (float*)d_out;

    const int smem_main = 64*ROWQ*16*2 + 32*ROWQ*16
                        + (NRAND*65 + 64 + 64 + 4*65) * (int)sizeof(float);
    cudaFuncSetAttribute(k_main, cudaFuncAttributeMaxDynamicSharedMemorySize, smem_main);

    k_norm_t<<<BB*NN/32, 256>>>(rgb);
    k_main<<<BB*NN/64, 256, smem_main>>>(dep, proj, ridx, valid);
    k_hard<<<BB*NPOS, 256>>>(proj, offu, offv, valid, out);
}